// round 3
// baseline (speedup 1.0000x reference)
#include <cuda_runtime.h>
#include <cuda_bf16.h>
#include <math.h>

#define TT 128
#define BB 512
#define HH 256
#define MM 64

// ---------------- device scratch (no allocation allowed) ----------------
__device__ float g_sentW[(size_t)TT * BB * HH];            // 64 MB: stories @ W
__device__ __nv_bfloat16 g_Uthi[HH * HH];                  // U^T hi  [n][k]
__device__ __nv_bfloat16 g_Utlo[HH * HH];                  // U^T lo
__device__ __nv_bfloat16 g_Wthi[HH * HH];                  // W^T hi
__device__ __nv_bfloat16 g_Wtlo[HH * HH];                  // W^T lo

// ---------------- smem geometry ----------------
// A (state): [128 rows][264 bf16] hi + lo. stride 264 bf16 = 132 b32 == 4 mod 32.
#define SA_STR 264
#define SA_BYTES (128 * SA_STR * 2)            // 67584 per split
// B chunk: [256 n][40 bf16] (k-chunk 32 + pad 8). stride 40 bf16 = 20 b32.
#define SBC_STR 40
#define SBC_BYTES (256 * SBC_STR * 2)          // 20480 per split
#define OFF_AHI 0
#define OFF_ALO SA_BYTES
#define OFF_B (2 * SA_BYTES)                   // 135168; 2 bufs x (hi,lo)
#define OFF_F32 (OFF_B + 4 * SBC_BYTES)        // 217088
// f32 area: keys[256], kc[256], pa[256], gm[128], rs[512]
#define SMEM_TOTAL (OFF_F32 + (256 + 256 + 256 + 128 + 512) * 4)   // 222720

// ---------------- PTX helpers ----------------
__device__ __forceinline__ unsigned smem_u32(const void* p) {
    return (unsigned)__cvta_generic_to_shared(p);
}
__device__ __forceinline__ void ldsm_x4(unsigned addr, unsigned& r0, unsigned& r1, unsigned& r2, unsigned& r3) {
    asm volatile("ldmatrix.sync.aligned.m8n8.x4.shared.b16 {%0,%1,%2,%3}, [%4];"
                 : "=r"(r0), "=r"(r1), "=r"(r2), "=r"(r3) : "r"(addr));
}
__device__ __forceinline__ void mma16816(float* c, const unsigned* a, unsigned b0, unsigned b1) {
    asm volatile("mma.sync.aligned.m16n8k16.row.col.f32.bf16.bf16.f32 "
                 "{%0,%1,%2,%3}, {%4,%5,%6,%7}, {%8,%9}, {%0,%1,%2,%3};"
                 : "+f"(c[0]), "+f"(c[1]), "+f"(c[2]), "+f"(c[3])
                 : "r"(a[0]), "r"(a[1]), "r"(a[2]), "r"(a[3]), "r"(b0), "r"(b1));
}
__device__ __forceinline__ void cpasync16(unsigned dst, const void* src) {
    asm volatile("cp.async.cg.shared.global [%0], [%1], 16;" :: "r"(dst), "l"(src));
}
__device__ __forceinline__ unsigned pack2(__nv_bfloat16 a, __nv_bfloat16 b) {
    unsigned short ua = *reinterpret_cast<unsigned short*>(&a);
    unsigned short ub = *reinterpret_cast<unsigned short*>(&b);
    return (unsigned)ua | ((unsigned)ub << 16);
}
__device__ __forceinline__ void split8(float4 v0, float4 v1, uint4& h, uint4& l) {
    float f[8] = {v0.x, v0.y, v0.z, v0.w, v1.x, v1.y, v1.z, v1.w};
    unsigned hh[4], ll[4];
#pragma unroll
    for (int j = 0; j < 4; j++) {
        float a = f[2 * j], b = f[2 * j + 1];
        __nv_bfloat16 ha = __float2bfloat16(a), hb = __float2bfloat16(b);
        __nv_bfloat16 la = __float2bfloat16(a - __bfloat162float(ha));
        __nv_bfloat16 lb = __float2bfloat16(b - __bfloat162float(hb));
        hh[j] = pack2(ha, hb);
        ll[j] = pack2(la, lb);
    }
    h = make_uint4(hh[0], hh[1], hh[2], hh[3]);
    l = make_uint4(ll[0], ll[1], ll[2], ll[3]);
}

// ---------------- prep: transpose + hi/lo split of U, W ----------------
__global__ void split_transpose_kernel(const float* __restrict__ src,
                                       __nv_bfloat16* __restrict__ hi,
                                       __nv_bfloat16* __restrict__ lo) {
    int idx = blockIdx.x * 256 + threadIdx.x;
    int n = idx >> 8, k = idx & 255;
    float x = src[k * 256 + n];
    __nv_bfloat16 h = __float2bfloat16(x);
    hi[idx] = h;
    lo[idx] = __float2bfloat16(x - __bfloat162float(h));
}

// ---------------- shared mma machinery ----------------
__device__ __forceinline__ void stage_A_gmem(const float* __restrict__ Asrc,
                                             char* sm, int tid) {
    __nv_bfloat16* sAhi = (__nv_bfloat16*)(sm + OFF_AHI);
    __nv_bfloat16* sAlo = (__nv_bfloat16*)(sm + OFF_ALO);
    for (int i = tid; i < 128 * 32; i += 512) {
        int row = i >> 5, kq = (i & 31) << 3;
        const float* p = Asrc + row * 256 + kq;
        float4 v0 = *(const float4*)p;
        float4 v1 = *(const float4*)(p + 4);
        uint4 h, l;
        split8(v0, v1, h, l);
        *(uint4*)(sAhi + row * SA_STR + kq) = h;
        *(uint4*)(sAlo + row * SA_STR + kq) = l;
    }
}

__device__ __forceinline__ void stage_B_chunk(char* sm, const __nv_bfloat16* __restrict__ Bthi,
                                              const __nv_bfloat16* __restrict__ Btlo,
                                              int buf, int kt, int tid) {
    __nv_bfloat16* bh = (__nv_bfloat16*)(sm + OFF_B + buf * 2 * SBC_BYTES);
    __nv_bfloat16* bl = (__nv_bfloat16*)(sm + OFF_B + buf * 2 * SBC_BYTES + SBC_BYTES);
    for (int i = tid; i < 1024; i += 512) {
        int n = i >> 2, g = (i & 3) << 3;
        cpasync16(smem_u32(bh + n * SBC_STR + g), Bthi + n * 256 + kt + g);
        cpasync16(smem_u32(bl + n * SBC_STR + g), Btlo + n * 256 + kt + g);
    }
}

// acc += A(state, smem hi/lo) @ B^T (gmem hi/lo), 128x256x256, 3-pass bf16 split.
// k=32 chunks, cp.async double-buffered.
__device__ __forceinline__ void run_mma(char* sm, const __nv_bfloat16* __restrict__ Bthi,
                                        const __nv_bfloat16* __restrict__ Btlo,
                                        float acc[2][8][4]) {
    const int tid = threadIdx.x;
    const int lane = tid & 31, wid = tid >> 5;
    const int wr = wid >> 2, wc = wid & 3;
    const int rb = wr * 32;
    const int a_lr = ((lane >> 3) & 1) * 8 + (lane & 7);
    const int a_lc = ((lane >> 4) & 1) * 8;
    const int b_nr = ((lane >> 4) << 3) + (lane & 7);
    const int b_kc = ((lane >> 3) & 1) << 3;
    const unsigned sAhiU = smem_u32(sm + OFF_AHI);
    const unsigned sAloU = smem_u32(sm + OFF_ALO);
    const unsigned sB0 = smem_u32(sm + OFF_B);

#pragma unroll
    for (int i = 0; i < 2; i++)
#pragma unroll
        for (int j = 0; j < 8; j++)
#pragma unroll
            for (int q = 0; q < 4; q++) acc[i][j][q] = 0.f;

    stage_B_chunk(sm, Bthi, Btlo, 0, 0, tid);
    asm volatile("cp.async.commit_group;");

#pragma unroll 2
    for (int c = 0; c < 8; c++) {
        if (c < 7) {
            stage_B_chunk(sm, Bthi, Btlo, (c + 1) & 1, (c + 1) * 32, tid);
            asm volatile("cp.async.commit_group;");
            asm volatile("cp.async.wait_group 1;");
        } else {
            asm volatile("cp.async.wait_group 0;");
        }
        __syncthreads();
        const unsigned sBhiU = sB0 + (c & 1) * 2 * SBC_BYTES;
        const unsigned sBloU = sBhiU + SBC_BYTES;
#pragma unroll
        for (int ks = 0; ks < 2; ks++) {
            int kA = c * 32 + ks * 16;
            unsigned Ah[2][4], Al[2][4];
#pragma unroll
            for (int mi = 0; mi < 2; mi++) {
                unsigned aoff = (unsigned)((rb + mi * 16 + a_lr) * SA_STR + kA + a_lc) * 2;
                ldsm_x4(sAhiU + aoff, Ah[mi][0], Ah[mi][1], Ah[mi][2], Ah[mi][3]);
                ldsm_x4(sAloU + aoff, Al[mi][0], Al[mi][1], Al[mi][2], Al[mi][3]);
            }
#pragma unroll
            for (int np = 0; np < 4; np++) {
                unsigned boff = (unsigned)((wc * 64 + np * 16 + b_nr) * SBC_STR + ks * 16 + b_kc) * 2;
                unsigned Bh[4], Bl[4];
                ldsm_x4(sBhiU + boff, Bh[0], Bh[1], Bh[2], Bh[3]);
                ldsm_x4(sBloU + boff, Bl[0], Bl[1], Bl[2], Bl[3]);
#pragma unroll
                for (int mi = 0; mi < 2; mi++) {
#pragma unroll
                    for (int nj = 0; nj < 2; nj++) {
                        float* cc = acc[mi][np * 2 + nj];
                        mma16816(cc, Ah[mi], Bh[2 * nj], Bh[2 * nj + 1]);
                        mma16816(cc, Ah[mi], Bl[2 * nj], Bl[2 * nj + 1]);
                        mma16816(cc, Al[mi], Bh[2 * nj], Bh[2 * nj + 1]);
                    }
                }
            }
        }
        __syncthreads();
    }
}

// ---------------- sentW precompute: C[row0+128][256] = stories @ W ----------------
__global__ __launch_bounds__(512, 1) void tc_gemm_kernel(const float* __restrict__ Asrc,
                                                         float* __restrict__ Cout) {
    extern __shared__ char sm[];
    const int tid = threadIdx.x;
    const int lane = tid & 31, wid = tid >> 5;
    const int wr = wid >> 2, wc = wid & 3;
    const int rb = wr * 32;
    const size_t row0 = (size_t)blockIdx.x * 128;

    stage_A_gmem(Asrc + row0 * 256, sm, tid);
    __syncthreads();

    float acc[2][8][4];
    run_mma(sm, g_Wthi, g_Wtlo, acc);

    const int gid = lane >> 2, tig = lane & 3;
#pragma unroll
    for (int mi = 0; mi < 2; mi++) {
        int r0 = rb + mi * 16 + gid, r1 = r0 + 8;
#pragma unroll
        for (int nt = 0; nt < 8; nt++) {
            int C = wc * 64 + nt * 8 + tig * 2;
            float* cc = acc[mi][nt];
            *(float2*)(Cout + (row0 + r0) * 256 + C) = make_float2(cc[0], cc[1]);
            *(float2*)(Cout + (row0 + r1) * 256 + C) = make_float2(cc[2], cc[3]);
        }
    }
}

// ---------------- the persistent recurrence kernel ----------------
// CTA = (m = blockIdx.y, 128 b-rows at blockIdx.x*128). State lives in smem
// (bf16 hi/lo) across all TT steps. Writes gates each step and the final
// memory tile at the end, both directly into d_out.
__global__ __launch_bounds__(512, 1) void persist_kernel(const float* __restrict__ stories,
                                                         const float* __restrict__ mask,
                                                         const float* __restrict__ keys,
                                                         const float* __restrict__ V,
                                                         const float* __restrict__ prelu_a,
                                                         float* __restrict__ out) {
    extern __shared__ char sm[];
    __nv_bfloat16* sAhi = (__nv_bfloat16*)(sm + OFF_AHI);
    __nv_bfloat16* sAlo = (__nv_bfloat16*)(sm + OFF_ALO);
    float* sKeys = (float*)(sm + OFF_F32);
    float* sKC   = sKeys + 256;
    float* sPA   = sKC + 256;
    float* sGm   = sPA + 256;
    float* sRS   = sGm + 128;

    const int tid = threadIdx.x;
    const int lane = tid & 31, wid = tid >> 5;
    const int wr = wid >> 2, wc = wid & 3;
    const int rb = wr * 32;
    const int gid = lane >> 2, tig = lane & 3;
    const int m = blockIdx.y;
    const int b0 = blockIdx.x * 128;

    float* __restrict__ gates_out = out + (size_t)MM * BB * HH;
    float* __restrict__ finmem = out;

    if (tid < 256) {
        sKeys[tid] = keys[m * HH + tid];
        sPA[tid]   = prelu_a[tid];
    }
    // keycand row: kc[c] = sum_k keys[m,k] * V[k,c]
    {
        int col = tid >> 1, half = tid & 1;
        const float* kp = keys + m * HH + half * 128;
        const float* vp = V + (size_t)half * 128 * HH + col;
        float p = 0.f;
#pragma unroll 8
        for (int k = 0; k < 128; k++) p += kp[k] * vp[(size_t)k * HH];
        p += __shfl_xor_sync(0xffffffffu, p, 1);
        if (half == 0) sKC[col] = p;
    }
    // init state: every row = keys[m]
    for (int i = tid; i < 128 * 32; i += 512) {
        int row = i >> 5, kq = (i & 31) << 3;
        float4 v0 = *(const float4*)(keys + m * HH + kq);
        float4 v1 = *(const float4*)(keys + m * HH + kq + 4);
        uint4 h, l;
        split8(v0, v1, h, l);
        *(uint4*)(sAhi + row * SA_STR + kq) = h;
        *(uint4*)(sAlo + row * SA_STR + kq) = l;
    }
    __syncthreads();

    for (int t = 0; t < TT; t++) {
        // ---- gate: sigmoid(dot(mem_row + keys, sent_row)) ----
        {
            int gr = tid >> 2, gq = tid & 3;
            const float* srow = stories + ((size_t)t * BB + b0 + gr) * HH + gq * 64;
            float p = 0.f;
#pragma unroll
            for (int kk = 0; kk < 64; kk += 2) {
                int k = gq * 64 + kk;
                __nv_bfloat162 h2 = *(__nv_bfloat162*)(sAhi + gr * SA_STR + k);
                __nv_bfloat162 l2 = *(__nv_bfloat162*)(sAlo + gr * SA_STR + k);
                float m0 = __bfloat162float(h2.x) + __bfloat162float(l2.x);
                float m1 = __bfloat162float(h2.y) + __bfloat162float(l2.y);
                p += (m0 + sKeys[k]) * srow[kk] + (m1 + sKeys[k + 1]) * srow[kk + 1];
            }
            p += __shfl_xor_sync(0xffffffffu, p, 1);
            p += __shfl_xor_sync(0xffffffffu, p, 2);
            if (gq == 0) {
                float g = 1.0f / (1.0f + expf(-p));
                gates_out[((size_t)t * MM + m) * BB + b0 + gr] = g;
                sGm[gr] = g * mask[t * BB + b0 + gr];
            }
        }

        // ---- acc = state @ U ----
        float acc[2][8][4];
        run_mma(sm, g_Uthi, g_Utlo, acc);   // contains syncthreads (orders sGm too)

        // ---- epilogue: cand=prelu(acc+kc+sw); mem'=normalize(mem + g*m*cand) ----
        const float* __restrict__ swbase = g_sentW + ((size_t)t * BB + b0) * HH;
#pragma unroll
        for (int mi = 0; mi < 2; mi++) {
            int r0 = rb + mi * 16 + gid, r1 = r0 + 8;
            float gm0 = sGm[r0], gm1 = sGm[r1];
            float ss0 = 0.f, ss1 = 0.f;
#pragma unroll
            for (int nt = 0; nt < 8; nt++) {
                int C = wc * 64 + nt * 8 + tig * 2;
                float2 kc = *(const float2*)(sKC + C);
                float2 pa = *(const float2*)(sPA + C);
                float2 sw0 = *(const float2*)(swbase + (size_t)r0 * 256 + C);
                float2 sw1 = *(const float2*)(swbase + (size_t)r1 * 256 + C);
                __nv_bfloat162 h0 = *(__nv_bfloat162*)(sAhi + r0 * SA_STR + C);
                __nv_bfloat162 l0 = *(__nv_bfloat162*)(sAlo + r0 * SA_STR + C);
                __nv_bfloat162 h1 = *(__nv_bfloat162*)(sAhi + r1 * SA_STR + C);
                __nv_bfloat162 l1 = *(__nv_bfloat162*)(sAlo + r1 * SA_STR + C);
                float om0x = __bfloat162float(h0.x) + __bfloat162float(l0.x);
                float om0y = __bfloat162float(h0.y) + __bfloat162float(l0.y);
                float om1x = __bfloat162float(h1.x) + __bfloat162float(l1.x);
                float om1y = __bfloat162float(h1.y) + __bfloat162float(l1.y);
                float* cc = acc[mi][nt];
                float v;
                v = cc[0] + kc.x + sw0.x; v = (v >= 0.f) ? v : pa.x * v; v = om0x + gm0 * v; ss0 += v * v; cc[0] = v;
                v = cc[1] + kc.y + sw0.y; v = (v >= 0.f) ? v : pa.y * v; v = om0y + gm0 * v; ss0 += v * v; cc[1] = v;
                v = cc[2] + kc.x + sw1.x; v = (v >= 0.f) ? v : pa.x * v; v = om1x + gm1 * v; ss1 += v * v; cc[2] = v;
                v = cc[3] + kc.y + sw1.y; v = (v >= 0.f) ? v : pa.y * v; v = om1y + gm1 * v; ss1 += v * v; cc[3] = v;
            }
            ss0 += __shfl_xor_sync(0xffffffffu, ss0, 1);
            ss0 += __shfl_xor_sync(0xffffffffu, ss0, 2);
            ss1 += __shfl_xor_sync(0xffffffffu, ss1, 1);
            ss1 += __shfl_xor_sync(0xffffffffu, ss1, 2);
            if (tig == 0) {
                sRS[r0 * 4 + wc] = ss0;
                sRS[r1 * 4 + wc] = ss1;
            }
        }
        __syncthreads();

#pragma unroll
        for (int mi = 0; mi < 2; mi++) {
            int r0 = rb + mi * 16 + gid, r1 = r0 + 8;
            float s0 = sRS[r0 * 4 + 0] + sRS[r0 * 4 + 1] + sRS[r0 * 4 + 2] + sRS[r0 * 4 + 3];
            float s1 = sRS[r1 * 4 + 0] + sRS[r1 * 4 + 1] + sRS[r1 * 4 + 2] + sRS[r1 * 4 + 3];
            float sc0 = 1.0f / fmaxf(sqrtf(s0), 1e-12f);
            float sc1 = 1.0f / fmaxf(sqrtf(s1), 1e-12f);
#pragma unroll
            for (int nt = 0; nt < 8; nt++) {
                int C = wc * 64 + nt * 8 + tig * 2;
                float* cc = acc[mi][nt];
                float n0x = cc[0] * sc0, n0y = cc[1] * sc0;
                float n1x = cc[2] * sc1, n1y = cc[3] * sc1;
                __nv_bfloat16 h0x = __float2bfloat16(n0x), h0y = __float2bfloat16(n0y);
                __nv_bfloat16 h1x = __float2bfloat16(n1x), h1y = __float2bfloat16(n1y);
                __nv_bfloat16 l0x = __float2bfloat16(n0x - __bfloat162float(h0x));
                __nv_bfloat16 l0y = __float2bfloat16(n0y - __bfloat162float(h0y));
                __nv_bfloat16 l1x = __float2bfloat16(n1x - __bfloat162float(h1x));
                __nv_bfloat16 l1y = __float2bfloat16(n1y - __bfloat162float(h1y));
                *(unsigned*)(sAhi + r0 * SA_STR + C) = pack2(h0x, h0y);
                *(unsigned*)(sAlo + r0 * SA_STR + C) = pack2(l0x, l0y);
                *(unsigned*)(sAhi + r1 * SA_STR + C) = pack2(h1x, h1y);
                *(unsigned*)(sAlo + r1 * SA_STR + C) = pack2(l1x, l1y);
            }
        }
        __syncthreads();
    }

    // ---- final memory tile -> d_out ----
    for (int i = tid; i < 128 * 256; i += 512) {
        int row = i >> 8, col = i & 255;
        float v = __bfloat162float(sAhi[row * SA_STR + col]) + __bfloat162float(sAlo[row * SA_STR + col]);
        finmem[((size_t)m * BB + b0 + row) * HH + col] = v;
    }
}

// ---------------------------------------------------------------------------
extern "C" void kernel_launch(void* const* d_in, const int* in_sizes, int n_in,
                              void* d_out, int out_size) {
    const float* stories = (const float*)d_in[0];
    const float* mask    = (const float*)d_in[1];
    const float* keys    = (const float*)d_in[2];
    const float* U       = (const float*)d_in[3];
    const float* W       = (const float*)d_in[4];
    const float* V       = (const float*)d_in[5];
    const float* prelu_a = (const float*)d_in[6];
    float* out = (float*)d_out;

    static bool attr_done = false;
    if (!attr_done) {
        cudaFuncSetAttribute(tc_gemm_kernel, cudaFuncAttributeMaxDynamicSharedMemorySize, SMEM_TOTAL);
        cudaFuncSetAttribute(persist_kernel, cudaFuncAttributeMaxDynamicSharedMemorySize, SMEM_TOTAL);
        attr_done = true;
    }

    __nv_bfloat16 *uthi, *utlo, *wthi, *wtlo;
    cudaGetSymbolAddress((void**)&uthi, g_Uthi);
    cudaGetSymbolAddress((void**)&utlo, g_Utlo);
    cudaGetSymbolAddress((void**)&wthi, g_Wthi);
    cudaGetSymbolAddress((void**)&wtlo, g_Wtlo);
    float* sentw;
    cudaGetSymbolAddress((void**)&sentw, g_sentW);

    split_transpose_kernel<<<256, 256>>>(U, uthi, utlo);
    split_transpose_kernel<<<256, 256>>>(W, wthi, wtlo);

    // sentW[t,b,:] = stories[t,b,:] @ W for all t (one big GEMM)
    tc_gemm_kernel<<<(TT * BB) / 128, 512, SMEM_TOTAL>>>(stories, sentw);

    // whole recurrence in one persistent launch
    dim3 grid(BB / 128, MM);
    persist_kernel<<<grid, 512, SMEM_TOTAL>>>(stories, mask, keys, V, prelu_a, out);
}

// round 4
// speedup vs baseline: 1.0876x; 1.0876x over previous
#include <cuda_runtime.h>
#include <cuda_bf16.h>
#include <math.h>

#define TT 128
#define BB 512
#define HH 256
#define MM 64

// ---------------- device scratch (no allocation allowed) ----------------
__device__ float g_sentW[(size_t)TT * BB * HH];            // 64 MB: stories @ W
__device__ __nv_bfloat16 g_Uthi[HH * HH];                  // U^T hi  [n][k]
__device__ __nv_bfloat16 g_Utlo[HH * HH];                  // U^T lo
__device__ __nv_bfloat16 g_Wthi[HH * HH];                  // W^T hi
__device__ __nv_bfloat16 g_Wtlo[HH * HH];                  // W^T lo

// ================= tc_gemm (sentW precompute) smem layout (R3, unchanged) ==
#define SA_STR 264
#define SA_BYTES (128 * SA_STR * 2)
#define SBC_STR 40
#define SBC_BYTES (256 * SBC_STR * 2)
#define OFF_AHI 0
#define OFF_ALO SA_BYTES
#define OFF_B (2 * SA_BYTES)
#define OFF_F32 (OFF_B + 4 * SBC_BYTES)
#define G_SMEM (OFF_F32 + 1024)

// ================= persist kernel smem layout (64-row tile) ================
#define P_SA_STR 264
#define P_SA_SPLIT (64 * P_SA_STR * 2)         // 33792 B per split
#define P_OFF_AHI 0
#define P_OFF_ALO P_SA_SPLIT                   // 33792
#define P_OFF_BH  (2 * P_SA_SPLIT)             // 67584 ; resident U^T hi [256][264]
#define P_BH_STR 264
#define P_BH_BYTES (256 * P_BH_STR * 2)        // 135168
#define P_OFF_BL  (P_OFF_BH + P_BH_BYTES)      // 202752 ; streamed lo chunk [256][40]
#define P_BL_STR 40
#define P_BL_BYTES (256 * P_BL_STR * 2)        // 20480
#define P_OFF_F32 (P_OFF_BL + P_BL_BYTES)      // 223232
// f32 area: keys[256], kc[256], pa[256], gm[64], rs[256]
#define P_SMEM (P_OFF_F32 + (256 + 256 + 256 + 64 + 256) * 4)   // 227584

// ---------------- PTX helpers ----------------
__device__ __forceinline__ unsigned smem_u32(const void* p) {
    return (unsigned)__cvta_generic_to_shared(p);
}
__device__ __forceinline__ void ldsm_x4(unsigned addr, unsigned& r0, unsigned& r1, unsigned& r2, unsigned& r3) {
    asm volatile("ldmatrix.sync.aligned.m8n8.x4.shared.b16 {%0,%1,%2,%3}, [%4];"
                 : "=r"(r0), "=r"(r1), "=r"(r2), "=r"(r3) : "r"(addr));
}
__device__ __forceinline__ void mma16816(float* c, const unsigned* a, unsigned b0, unsigned b1) {
    asm volatile("mma.sync.aligned.m16n8k16.row.col.f32.bf16.bf16.f32 "
                 "{%0,%1,%2,%3}, {%4,%5,%6,%7}, {%8,%9}, {%0,%1,%2,%3};"
                 : "+f"(c[0]), "+f"(c[1]), "+f"(c[2]), "+f"(c[3])
                 : "r"(a[0]), "r"(a[1]), "r"(a[2]), "r"(a[3]), "r"(b0), "r"(b1));
}
__device__ __forceinline__ void cpasync16(unsigned dst, const void* src) {
    asm volatile("cp.async.cg.shared.global [%0], [%1], 16;" :: "r"(dst), "l"(src));
}
__device__ __forceinline__ unsigned pack2(__nv_bfloat16 a, __nv_bfloat16 b) {
    unsigned short ua = *reinterpret_cast<unsigned short*>(&a);
    unsigned short ub = *reinterpret_cast<unsigned short*>(&b);
    return (unsigned)ua | ((unsigned)ub << 16);
}
__device__ __forceinline__ void split8(float4 v0, float4 v1, uint4& h, uint4& l) {
    float f[8] = {v0.x, v0.y, v0.z, v0.w, v1.x, v1.y, v1.z, v1.w};
    unsigned hh[4], ll[4];
#pragma unroll
    for (int j = 0; j < 4; j++) {
        float a = f[2 * j], b = f[2 * j + 1];
        __nv_bfloat16 ha = __float2bfloat16(a), hb = __float2bfloat16(b);
        __nv_bfloat16 la = __float2bfloat16(a - __bfloat162float(ha));
        __nv_bfloat16 lb = __float2bfloat16(b - __bfloat162float(hb));
        hh[j] = pack2(ha, hb);
        ll[j] = pack2(la, lb);
    }
    h = make_uint4(hh[0], hh[1], hh[2], hh[3]);
    l = make_uint4(ll[0], ll[1], ll[2], ll[3]);
}

// ---------------- prep: transpose + hi/lo split of U, W ----------------
__global__ void split_transpose_kernel(const float* __restrict__ src,
                                       __nv_bfloat16* __restrict__ hi,
                                       __nv_bfloat16* __restrict__ lo) {
    int idx = blockIdx.x * 256 + threadIdx.x;
    int n = idx >> 8, k = idx & 255;
    float x = src[k * 256 + n];
    __nv_bfloat16 h = __float2bfloat16(x);
    hi[idx] = h;
    lo[idx] = __float2bfloat16(x - __bfloat162float(h));
}

// ================= tc_gemm machinery (R3, 128-row tiles) ===================
__device__ __forceinline__ void g_stage_A(const float* __restrict__ Asrc, char* sm, int tid) {
    __nv_bfloat16* sAhi = (__nv_bfloat16*)(sm + OFF_AHI);
    __nv_bfloat16* sAlo = (__nv_bfloat16*)(sm + OFF_ALO);
    for (int i = tid; i < 128 * 32; i += 512) {
        int row = i >> 5, kq = (i & 31) << 3;
        const float* p = Asrc + row * 256 + kq;
        float4 v0 = *(const float4*)p;
        float4 v1 = *(const float4*)(p + 4);
        uint4 h, l;
        split8(v0, v1, h, l);
        *(uint4*)(sAhi + row * SA_STR + kq) = h;
        *(uint4*)(sAlo + row * SA_STR + kq) = l;
    }
}
__device__ __forceinline__ void g_stage_B(char* sm, const __nv_bfloat16* __restrict__ Bthi,
                                          const __nv_bfloat16* __restrict__ Btlo,
                                          int buf, int kt, int tid) {
    __nv_bfloat16* bh = (__nv_bfloat16*)(sm + OFF_B + buf * 2 * SBC_BYTES);
    __nv_bfloat16* bl = (__nv_bfloat16*)(sm + OFF_B + buf * 2 * SBC_BYTES + SBC_BYTES);
    for (int i = tid; i < 1024; i += 512) {
        int n = i >> 2, g = (i & 3) << 3;
        cpasync16(smem_u32(bh + n * SBC_STR + g), Bthi + n * 256 + kt + g);
        cpasync16(smem_u32(bl + n * SBC_STR + g), Btlo + n * 256 + kt + g);
    }
}

__global__ __launch_bounds__(512, 1) void tc_gemm_kernel(const float* __restrict__ Asrc,
                                                         float* __restrict__ Cout) {
    extern __shared__ char sm[];
    const int tid = threadIdx.x;
    const int lane = tid & 31, wid = tid >> 5;
    const int wr = wid >> 2, wc = wid & 3;
    const int rb = wr * 32;
    const size_t row0 = (size_t)blockIdx.x * 128;
    const int a_lr = ((lane >> 3) & 1) * 8 + (lane & 7);
    const int a_lc = ((lane >> 4) & 1) * 8;
    const int b_nr = ((lane >> 4) << 3) + (lane & 7);
    const int b_kc = ((lane >> 3) & 1) << 3;
    const unsigned sAhiU = smem_u32(sm + OFF_AHI);
    const unsigned sAloU = smem_u32(sm + OFF_ALO);
    const unsigned sB0 = smem_u32(sm + OFF_B);

    g_stage_A(Asrc + row0 * 256, sm, tid);
    __syncthreads();

    float acc[2][8][4];
#pragma unroll
    for (int i = 0; i < 2; i++)
#pragma unroll
        for (int j = 0; j < 8; j++)
#pragma unroll
            for (int q = 0; q < 4; q++) acc[i][j][q] = 0.f;

    g_stage_B(sm, g_Wthi, g_Wtlo, 0, 0, tid);
    asm volatile("cp.async.commit_group;");

#pragma unroll 2
    for (int c = 0; c < 8; c++) {
        if (c < 7) {
            g_stage_B(sm, g_Wthi, g_Wtlo, (c + 1) & 1, (c + 1) * 32, tid);
            asm volatile("cp.async.commit_group;");
            asm volatile("cp.async.wait_group 1;");
        } else {
            asm volatile("cp.async.wait_group 0;");
        }
        __syncthreads();
        const unsigned sBhiU = sB0 + (c & 1) * 2 * SBC_BYTES;
        const unsigned sBloU = sBhiU + SBC_BYTES;
#pragma unroll
        for (int ks = 0; ks < 2; ks++) {
            int kA = c * 32 + ks * 16;
            unsigned Ah[2][4], Al[2][4];
#pragma unroll
            for (int mi = 0; mi < 2; mi++) {
                unsigned aoff = (unsigned)((rb + mi * 16 + a_lr) * SA_STR + kA + a_lc) * 2;
                ldsm_x4(sAhiU + aoff, Ah[mi][0], Ah[mi][1], Ah[mi][2], Ah[mi][3]);
                ldsm_x4(sAloU + aoff, Al[mi][0], Al[mi][1], Al[mi][2], Al[mi][3]);
            }
#pragma unroll
            for (int np = 0; np < 4; np++) {
                unsigned boff = (unsigned)((wc * 64 + np * 16 + b_nr) * SBC_STR + ks * 16 + b_kc) * 2;
                unsigned Bh[4], Bl[4];
                ldsm_x4(sBhiU + boff, Bh[0], Bh[1], Bh[2], Bh[3]);
                ldsm_x4(sBloU + boff, Bl[0], Bl[1], Bl[2], Bl[3]);
#pragma unroll
                for (int mi = 0; mi < 2; mi++) {
#pragma unroll
                    for (int nj = 0; nj < 2; nj++) {
                        float* cc = acc[mi][np * 2 + nj];
                        mma16816(cc, Ah[mi], Bh[2 * nj], Bh[2 * nj + 1]);
                        mma16816(cc, Ah[mi], Bl[2 * nj], Bl[2 * nj + 1]);
                        mma16816(cc, Al[mi], Bh[2 * nj], Bh[2 * nj + 1]);
                    }
                }
            }
        }
        __syncthreads();
    }

    const int gid = lane >> 2, tig = lane & 3;
#pragma unroll
    for (int mi = 0; mi < 2; mi++) {
        int r0 = rb + mi * 16 + gid, r1 = r0 + 8;
#pragma unroll
        for (int nt = 0; nt < 8; nt++) {
            int C = wc * 64 + nt * 8 + tig * 2;
            float* cc = acc[mi][nt];
            *(float2*)(Cout + (row0 + r0) * 256 + C) = make_float2(cc[0], cc[1]);
            *(float2*)(Cout + (row0 + r1) * 256 + C) = make_float2(cc[2], cc[3]);
        }
    }
}

// ================= persistent recurrence kernel ============================
// CTA = (m = blockIdx.y, 64 b-rows at blockIdx.x*64). 256 threads (8 warps:
// 2 row-groups x 4 col-groups). State (bf16 hi/lo) + full U^T-hi resident in
// smem for all TT steps; only U^T-lo streams per step (1/3 of mma work).
__global__ __launch_bounds__(256, 1) void persist_kernel(const float* __restrict__ stories,
                                                         const float* __restrict__ mask,
                                                         const float* __restrict__ keys,
                                                         const float* __restrict__ V,
                                                         const float* __restrict__ prelu_a,
                                                         float* __restrict__ out) {
    extern __shared__ char sm[];
    __nv_bfloat16* sAhi = (__nv_bfloat16*)(sm + P_OFF_AHI);
    __nv_bfloat16* sAlo = (__nv_bfloat16*)(sm + P_OFF_ALO);
    __nv_bfloat16* sBh  = (__nv_bfloat16*)(sm + P_OFF_BH);
    __nv_bfloat16* sBl  = (__nv_bfloat16*)(sm + P_OFF_BL);
    float* sKeys = (float*)(sm + P_OFF_F32);
    float* sKC   = sKeys + 256;
    float* sPA   = sKC + 256;
    float* sGm   = sPA + 256;       // [64]
    float* sRS   = sGm + 64;        // [64][4]

    const int tid = threadIdx.x;
    const int lane = tid & 31, wid = tid >> 5;
    const int wr = wid >> 2, wc = wid & 3;
    const int rb = wr * 32;
    const int gid = lane >> 2, tig = lane & 3;
    const int m = blockIdx.y;
    const int b0 = blockIdx.x * 64;

    const int a_lr = ((lane >> 3) & 1) * 8 + (lane & 7);
    const int a_lc = ((lane >> 4) & 1) * 8;
    const int b_nr = ((lane >> 4) << 3) + (lane & 7);
    const int b_kc = ((lane >> 3) & 1) << 3;
    const unsigned sAhiU = smem_u32(sAhi), sAloU = smem_u32(sAlo);
    const unsigned sBhU = smem_u32(sBh), sBlU = smem_u32(sBl);

    float* __restrict__ gates_out = out + (size_t)MM * BB * HH;
    float* __restrict__ finmem = out;

    sKeys[tid] = keys[m * HH + tid];
    sPA[tid]   = prelu_a[tid];
    // keycand: kc[col] = sum_k keys[m,k] * V[k,col]
    {
        float p = 0.f;
        const float* vp = V + tid;
        const float* kp = keys + m * HH;
#pragma unroll 8
        for (int k = 0; k < 256; k++) p += kp[k] * vp[(size_t)k * HH];
        sKC[tid] = p;
    }
    // resident U^T hi: sBh[n][k], stride 264
    for (int i = tid; i < 256 * 32; i += 256) {
        int n = i >> 5, g = (i & 31) << 3;
        *(uint4*)(sBh + n * P_BH_STR + g) = *(const uint4*)(g_Uthi + n * 256 + g);
    }
    // init state rows = keys[m]
    for (int i = tid; i < 64 * 32; i += 256) {
        int row = i >> 5, kq = (i & 31) << 3;
        float4 v0 = *(const float4*)(keys + m * HH + kq);
        float4 v1 = *(const float4*)(keys + m * HH + kq + 4);
        uint4 h, l;
        split8(v0, v1, h, l);
        *(uint4*)(sAhi + row * P_SA_STR + kq) = h;
        *(uint4*)(sAlo + row * P_SA_STR + kq) = l;
    }
    __syncthreads();

    for (int t = 0; t < TT; t++) {
        // prefetch U^T-lo chunk 0 (hides under gate + resident slab 0)
        for (int i = tid; i < 1024; i += 256) {
            int n = i >> 2, g = (i & 3) << 3;
            cpasync16(sBlU + (unsigned)(n * P_BL_STR + g) * 2, g_Utlo + n * 256 + g);
        }
        asm volatile("cp.async.commit_group;");

        // ---- gate: sigmoid(dot(mem_row + keys, sent_row)) ----
        {
            int gr = tid >> 2, gq = tid & 3;
            const float* srow = stories + ((size_t)t * BB + b0 + gr) * HH + gq * 64;
            float p = 0.f;
#pragma unroll
            for (int kk = 0; kk < 64; kk += 2) {
                int k = gq * 64 + kk;
                __nv_bfloat162 h2 = *(__nv_bfloat162*)(sAhi + gr * P_SA_STR + k);
                __nv_bfloat162 l2 = *(__nv_bfloat162*)(sAlo + gr * P_SA_STR + k);
                float m0 = __bfloat162float(h2.x) + __bfloat162float(l2.x);
                float m1 = __bfloat162float(h2.y) + __bfloat162float(l2.y);
                p += (m0 + sKeys[k]) * srow[kk] + (m1 + sKeys[k + 1]) * srow[kk + 1];
            }
            p += __shfl_xor_sync(0xffffffffu, p, 1);
            p += __shfl_xor_sync(0xffffffffu, p, 2);
            if (gq == 0) {
                float g = 1.0f / (1.0f + expf(-p));
                gates_out[((size_t)t * MM + m) * BB + b0 + gr] = g;
                sGm[gr] = g * mask[t * BB + b0 + gr];
            }
        }

        // ---- mma: acc = state @ U  (AhBh + AlBh resident, AhBl streamed) ----
        float acc[2][8][4];
#pragma unroll
        for (int i = 0; i < 2; i++)
#pragma unroll
            for (int j = 0; j < 8; j++)
#pragma unroll
                for (int q = 0; q < 4; q++) acc[i][j][q] = 0.f;

        for (int c = 0; c < 8; c++) {
            unsigned AhS[2][2][4];          // saved A-hi frags [ks][mi]
            // resident slab: barrier-free
#pragma unroll
            for (int ks = 0; ks < 2; ks++) {
                int kcol = c * 32 + ks * 16;
                unsigned Al[2][4];
#pragma unroll
                for (int mi = 0; mi < 2; mi++) {
                    unsigned aoff = (unsigned)((rb + mi * 16 + a_lr) * P_SA_STR + kcol + a_lc) * 2;
                    ldsm_x4(sAhiU + aoff, AhS[ks][mi][0], AhS[ks][mi][1], AhS[ks][mi][2], AhS[ks][mi][3]);
                    ldsm_x4(sAloU + aoff, Al[mi][0], Al[mi][1], Al[mi][2], Al[mi][3]);
                }
#pragma unroll
                for (int np = 0; np < 4; np++) {
                    unsigned boff = (unsigned)((wc * 64 + np * 16 + b_nr) * P_BH_STR + kcol + b_kc) * 2;
                    unsigned Bh[4];
                    ldsm_x4(sBhU + boff, Bh[0], Bh[1], Bh[2], Bh[3]);
#pragma unroll
                    for (int mi = 0; mi < 2; mi++) {
#pragma unroll
                        for (int nj = 0; nj < 2; nj++) {
                            float* cc = acc[mi][np * 2 + nj];
                            mma16816(cc, AhS[ks][mi], Bh[2 * nj], Bh[2 * nj + 1]);
                            mma16816(cc, Al[mi], Bh[2 * nj], Bh[2 * nj + 1]);
                        }
                    }
                }
            }
            // streamed lo pass for this chunk
            asm volatile("cp.async.wait_group 0;");
            __syncthreads();
#pragma unroll
            for (int ks = 0; ks < 2; ks++) {
#pragma unroll
                for (int np = 0; np < 4; np++) {
                    unsigned boff = (unsigned)((wc * 64 + np * 16 + b_nr) * P_BL_STR + ks * 16 + b_kc) * 2;
                    unsigned Bl[4];
                    ldsm_x4(sBlU + boff, Bl[0], Bl[1], Bl[2], Bl[3]);
#pragma unroll
                    for (int mi = 0; mi < 2; mi++) {
#pragma unroll
                        for (int nj = 0; nj < 2; nj++)
                            mma16816(acc[mi][np * 2 + nj], AhS[ks][mi], Bl[2 * nj], Bl[2 * nj + 1]);
                    }
                }
            }
            __syncthreads();
            if (c < 7) {
                int kt = (c + 1) * 32;
                for (int i = tid; i < 1024; i += 256) {
                    int n = i >> 2, g = (i & 3) << 3;
                    cpasync16(sBlU + (unsigned)(n * P_BL_STR + g) * 2, g_Utlo + n * 256 + kt + g);
                }
                asm volatile("cp.async.commit_group;");
            }
        }

        // ---- epilogue: cand=prelu(acc+kc+sw); mem'=normalize(mem + g*m*cand) ----
        const float* __restrict__ swbase = g_sentW + ((size_t)t * BB + b0) * HH;
#pragma unroll
        for (int mi = 0; mi < 2; mi++) {
            int r0 = rb + mi * 16 + gid, r1 = r0 + 8;
            float gm0 = sGm[r0], gm1 = sGm[r1];
            float ss0 = 0.f, ss1 = 0.f;
#pragma unroll
            for (int nt = 0; nt < 8; nt++) {
                int C = wc * 64 + nt * 8 + tig * 2;
                float2 kc = *(const float2*)(sKC + C);
                float2 pa = *(const float2*)(sPA + C);
                float2 sw0 = *(const float2*)(swbase + (size_t)r0 * 256 + C);
                float2 sw1 = *(const float2*)(swbase + (size_t)r1 * 256 + C);
                __nv_bfloat162 h0 = *(__nv_bfloat162*)(sAhi + r0 * P_SA_STR + C);
                __nv_bfloat162 l0 = *(__nv_bfloat162*)(sAlo + r0 * P_SA_STR + C);
                __nv_bfloat162 h1 = *(__nv_bfloat162*)(sAhi + r1 * P_SA_STR + C);
                __nv_bfloat162 l1 = *(__nv_bfloat162*)(sAlo + r1 * P_SA_STR + C);
                float om0x = __bfloat162float(h0.x) + __bfloat162float(l0.x);
                float om0y = __bfloat162float(h0.y) + __bfloat162float(l0.y);
                float om1x = __bfloat162float(h1.x) + __bfloat162float(l1.x);
                float om1y = __bfloat162float(h1.y) + __bfloat162float(l1.y);
                float* cc = acc[mi][nt];
                float v;
                v = cc[0] + kc.x + sw0.x; v = (v >= 0.f) ? v : pa.x * v; v = om0x + gm0 * v; ss0 += v * v; cc[0] = v;
                v = cc[1] + kc.y + sw0.y; v = (v >= 0.f) ? v : pa.y * v; v = om0y + gm0 * v; ss0 += v * v; cc[1] = v;
                v = cc[2] + kc.x + sw1.x; v = (v >= 0.f) ? v : pa.x * v; v = om1x + gm1 * v; ss1 += v * v; cc[2] = v;
                v = cc[3] + kc.y + sw1.y; v = (v >= 0.f) ? v : pa.y * v; v = om1y + gm1 * v; ss1 += v * v; cc[3] = v;
            }
            ss0 += __shfl_xor_sync(0xffffffffu, ss0, 1);
            ss0 += __shfl_xor_sync(0xffffffffu, ss0, 2);
            ss1 += __shfl_xor_sync(0xffffffffu, ss1, 1);
            ss1 += __shfl_xor_sync(0xffffffffu, ss1, 2);
            if (tig == 0) {
                sRS[r0 * 4 + wc] = ss0;
                sRS[r1 * 4 + wc] = ss1;
            }
        }
        __syncthreads();

#pragma unroll
        for (int mi = 0; mi < 2; mi++) {
            int r0 = rb + mi * 16 + gid, r1 = r0 + 8;
            float s0 = sRS[r0 * 4 + 0] + sRS[r0 * 4 + 1] + sRS[r0 * 4 + 2] + sRS[r0 * 4 + 3];
            float s1 = sRS[r1 * 4 + 0] + sRS[r1 * 4 + 1] + sRS[r1 * 4 + 2] + sRS[r1 * 4 + 3];
            float sc0 = 1.0f / fmaxf(sqrtf(s0), 1e-12f);
            float sc1 = 1.0f / fmaxf(sqrtf(s1), 1e-12f);
#pragma unroll
            for (int nt = 0; nt < 8; nt++) {
                int C = wc * 64 + nt * 8 + tig * 2;
                float* cc = acc[mi][nt];
                float n0x = cc[0] * sc0, n0y = cc[1] * sc0;
                float n1x = cc[2] * sc1, n1y = cc[3] * sc1;
                __nv_bfloat16 h0x = __float2bfloat16(n0x), h0y = __float2bfloat16(n0y);
                __nv_bfloat16 h1x = __float2bfloat16(n1x), h1y = __float2bfloat16(n1y);
                __nv_bfloat16 l0x = __float2bfloat16(n0x - __bfloat162float(h0x));
                __nv_bfloat16 l0y = __float2bfloat16(n0y - __bfloat162float(h0y));
                __nv_bfloat16 l1x = __float2bfloat16(n1x - __bfloat162float(h1x));
                __nv_bfloat16 l1y = __float2bfloat16(n1y - __bfloat162float(h1y));
                *(unsigned*)(sAhi + r0 * P_SA_STR + C) = pack2(h0x, h0y);
                *(unsigned*)(sAlo + r0 * P_SA_STR + C) = pack2(l0x, l0y);
                *(unsigned*)(sAhi + r1 * P_SA_STR + C) = pack2(h1x, h1y);
                *(unsigned*)(sAlo + r1 * P_SA_STR + C) = pack2(l1x, l1y);
            }
        }
        __syncthreads();
    }

    // ---- final memory tile -> d_out ----
    for (int i = tid; i < 64 * 256; i += 256) {
        int row = i >> 8, col = i & 255;
        float v = __bfloat162float(sAhi[row * P_SA_STR + col]) + __bfloat162float(sAlo[row * P_SA_STR + col]);
        finmem[((size_t)m * BB + b0 + row) * HH + col] = v;
    }
}

// ---------------------------------------------------------------------------
extern "C" void kernel_launch(void* const* d_in, const int* in_sizes, int n_in,
                              void* d_out, int out_size) {
    const float* stories = (const float*)d_in[0];
    const float* mask    = (const float*)d_in[1];
    const float* keys    = (const float*)d_in[2];
    const float* U       = (const float*)d_in[3];
    const float* W       = (const float*)d_in[4];
    const float* V       = (const float*)d_in[5];
    const float* prelu_a = (const float*)d_in[6];
    float* out = (float*)d_out;

    static bool attr_done = false;
    if (!attr_done) {
        cudaFuncSetAttribute(tc_gemm_kernel, cudaFuncAttributeMaxDynamicSharedMemorySize, G_SMEM);
        cudaFuncSetAttribute(persist_kernel, cudaFuncAttributeMaxDynamicSharedMemorySize, P_SMEM);
        attr_done = true;
    }

    __nv_bfloat16 *uthi, *utlo, *wthi, *wtlo;
    cudaGetSymbolAddress((void**)&uthi, g_Uthi);
    cudaGetSymbolAddress((void**)&utlo, g_Utlo);
    cudaGetSymbolAddress((void**)&wthi, g_Wthi);
    cudaGetSymbolAddress((void**)&wtlo, g_Wtlo);
    float* sentw;
    cudaGetSymbolAddress((void**)&sentw, g_sentW);

    split_transpose_kernel<<<256, 256>>>(U, uthi, utlo);
    split_transpose_kernel<<<256, 256>>>(W, wthi, wtlo);

    // sentW[t,b,:] = stories[t,b,:] @ W for all t (one big GEMM)
    tc_gemm_kernel<<<(TT * BB) / 128, 512, G_SMEM>>>(stories, sentw);

    // whole recurrence in one persistent launch (state resident in smem)
    dim3 grid(BB / 64, MM);
    persist_kernel<<<grid, 256, P_SMEM>>>(stories, mask, keys, V, prelu_a, out);
}

// round 5
// speedup vs baseline: 1.0880x; 1.0004x over previous
#include <cuda_runtime.h>
#include <cuda_bf16.h>
#include <math.h>

#define TT 128
#define BB 512
#define HH 256
#define MM 64

// ---------------- device scratch (no allocation allowed) ----------------
__device__ float g_sentW[(size_t)TT * BB * HH];            // 64 MB: stories @ W
__device__ __nv_bfloat16 g_Uthi[HH * HH];                  // U^T hi  [n][k]
__device__ __nv_bfloat16 g_Utlo[HH * HH];                  // U^T lo
__device__ __nv_bfloat16 g_Wthi[HH * HH];                  // W^T hi
__device__ __nv_bfloat16 g_Wtlo[HH * HH];                  // W^T lo

// ================= tc_gemm (sentW precompute) smem layout (R3, unchanged) ==
#define SA_STR 264
#define SA_BYTES (128 * SA_STR * 2)
#define SBC_STR 40
#define SBC_BYTES (256 * SBC_STR * 2)
#define OFF_AHI 0
#define OFF_ALO SA_BYTES
#define OFF_B (2 * SA_BYTES)
#define OFF_F32 (OFF_B + 4 * SBC_BYTES)
#define G_SMEM (OFF_F32 + 1024)

// ================= persist kernel smem layout (64-row tile) ================
#define P_SA_STR 264
#define P_SA_SPLIT (64 * P_SA_STR * 2)         // 33792 B per split
#define P_OFF_AHI 0
#define P_OFF_ALO P_SA_SPLIT                   // 33792
#define P_OFF_BH  (2 * P_SA_SPLIT)             // 67584 ; resident U^T hi [256][264]
#define P_BH_STR 264
#define P_BH_BYTES (256 * P_BH_STR * 2)        // 135168
#define P_OFF_BL  (P_OFF_BH + P_BH_BYTES)      // 202752 ; streamed lo chunk [256][40]
#define P_BL_STR 40
#define P_BL_BYTES (256 * P_BL_STR * 2)        // 20480
#define P_OFF_F32 (P_OFF_BL + P_BL_BYTES)      // 223232
// f32 area: keys[256], kc[256], pa[256], gm[64], rs[256]
#define P_SMEM (P_OFF_F32 + (256 + 256 + 256 + 64 + 256) * 4)   // 227584

// ---------------- PTX helpers ----------------
__device__ __forceinline__ unsigned smem_u32(const void* p) {
    return (unsigned)__cvta_generic_to_shared(p);
}
__device__ __forceinline__ void ldsm_x4(unsigned addr, unsigned& r0, unsigned& r1, unsigned& r2, unsigned& r3) {
    asm volatile("ldmatrix.sync.aligned.m8n8.x4.shared.b16 {%0,%1,%2,%3}, [%4];"
                 : "=r"(r0), "=r"(r1), "=r"(r2), "=r"(r3) : "r"(addr));
}
__device__ __forceinline__ void mma16816(float* c, const unsigned* a, unsigned b0, unsigned b1) {
    asm volatile("mma.sync.aligned.m16n8k16.row.col.f32.bf16.bf16.f32 "
                 "{%0,%1,%2,%3}, {%4,%5,%6,%7}, {%8,%9}, {%0,%1,%2,%3};"
                 : "+f"(c[0]), "+f"(c[1]), "+f"(c[2]), "+f"(c[3])
                 : "r"(a[0]), "r"(a[1]), "r"(a[2]), "r"(a[3]), "r"(b0), "r"(b1));
}
__device__ __forceinline__ void cpasync16(unsigned dst, const void* src) {
    asm volatile("cp.async.cg.shared.global [%0], [%1], 16;" :: "r"(dst), "l"(src));
}
__device__ __forceinline__ unsigned pack2(__nv_bfloat16 a, __nv_bfloat16 b) {
    unsigned short ua = *reinterpret_cast<unsigned short*>(&a);
    unsigned short ub = *reinterpret_cast<unsigned short*>(&b);
    return (unsigned)ua | ((unsigned)ub << 16);
}
__device__ __forceinline__ void split8(float4 v0, float4 v1, uint4& h, uint4& l) {
    float f[8] = {v0.x, v0.y, v0.z, v0.w, v1.x, v1.y, v1.z, v1.w};
    unsigned hh[4], ll[4];
#pragma unroll
    for (int j = 0; j < 4; j++) {
        float a = f[2 * j], b = f[2 * j + 1];
        __nv_bfloat16 ha = __float2bfloat16(a), hb = __float2bfloat16(b);
        __nv_bfloat16 la = __float2bfloat16(a - __bfloat162float(ha));
        __nv_bfloat16 lb = __float2bfloat16(b - __bfloat162float(hb));
        hh[j] = pack2(ha, hb);
        ll[j] = pack2(la, lb);
    }
    h = make_uint4(hh[0], hh[1], hh[2], hh[3]);
    l = make_uint4(ll[0], ll[1], ll[2], ll[3]);
}

// ---------------- prep: transpose + hi/lo split of U, W ----------------
__global__ void split_transpose_kernel(const float* __restrict__ src,
                                       __nv_bfloat16* __restrict__ hi,
                                       __nv_bfloat16* __restrict__ lo) {
    int idx = blockIdx.x * 256 + threadIdx.x;
    int n = idx >> 8, k = idx & 255;
    float x = src[k * 256 + n];
    __nv_bfloat16 h = __float2bfloat16(x);
    hi[idx] = h;
    lo[idx] = __float2bfloat16(x - __bfloat162float(h));
}

// ================= tc_gemm machinery (R3, 128-row tiles) ===================
__device__ __forceinline__ void g_stage_A(const float* __restrict__ Asrc, char* sm, int tid) {
    __nv_bfloat16* sAhi = (__nv_bfloat16*)(sm + OFF_AHI);
    __nv_bfloat16* sAlo = (__nv_bfloat16*)(sm + OFF_ALO);
    for (int i = tid; i < 128 * 32; i += 512) {
        int row = i >> 5, kq = (i & 31) << 3;
        const float* p = Asrc + row * 256 + kq;
        float4 v0 = *(const float4*)p;
        float4 v1 = *(const float4*)(p + 4);
        uint4 h, l;
        split8(v0, v1, h, l);
        *(uint4*)(sAhi + row * SA_STR + kq) = h;
        *(uint4*)(sAlo + row * SA_STR + kq) = l;
    }
}
__device__ __forceinline__ void g_stage_B(char* sm, const __nv_bfloat16* __restrict__ Bthi,
                                          const __nv_bfloat16* __restrict__ Btlo,
                                          int buf, int kt, int tid) {
    __nv_bfloat16* bh = (__nv_bfloat16*)(sm + OFF_B + buf * 2 * SBC_BYTES);
    __nv_bfloat16* bl = (__nv_bfloat16*)(sm + OFF_B + buf * 2 * SBC_BYTES + SBC_BYTES);
    for (int i = tid; i < 1024; i += 512) {
        int n = i >> 2, g = (i & 3) << 3;
        cpasync16(smem_u32(bh + n * SBC_STR + g), Bthi + n * 256 + kt + g);
        cpasync16(smem_u32(bl + n * SBC_STR + g), Btlo + n * 256 + kt + g);
    }
}

__global__ __launch_bounds__(512, 1) void tc_gemm_kernel(const float* __restrict__ Asrc,
                                                         float* __restrict__ Cout) {
    extern __shared__ char sm[];
    const int tid = threadIdx.x;
    const int lane = tid & 31, wid = tid >> 5;
    const int wr = wid >> 2, wc = wid & 3;
    const int rb = wr * 32;
    const size_t row0 = (size_t)blockIdx.x * 128;
    const int a_lr = ((lane >> 3) & 1) * 8 + (lane & 7);
    const int a_lc = ((lane >> 4) & 1) * 8;
    const int b_nr = ((lane >> 4) << 3) + (lane & 7);
    const int b_kc = ((lane >> 3) & 1) << 3;
    const unsigned sAhiU = smem_u32(sm + OFF_AHI);
    const unsigned sAloU = smem_u32(sm + OFF_ALO);
    const unsigned sB0 = smem_u32(sm + OFF_B);

    g_stage_A(Asrc + row0 * 256, sm, tid);
    __syncthreads();

    float acc[2][8][4];
#pragma unroll
    for (int i = 0; i < 2; i++)
#pragma unroll
        for (int j = 0; j < 8; j++)
#pragma unroll
            for (int q = 0; q < 4; q++) acc[i][j][q] = 0.f;

    g_stage_B(sm, g_Wthi, g_Wtlo, 0, 0, tid);
    asm volatile("cp.async.commit_group;");

#pragma unroll 2
    for (int c = 0; c < 8; c++) {
        if (c < 7) {
            g_stage_B(sm, g_Wthi, g_Wtlo, (c + 1) & 1, (c + 1) * 32, tid);
            asm volatile("cp.async.commit_group;");
            asm volatile("cp.async.wait_group 1;");
        } else {
            asm volatile("cp.async.wait_group 0;");
        }
        __syncthreads();
        const unsigned sBhiU = sB0 + (c & 1) * 2 * SBC_BYTES;
        const unsigned sBloU = sBhiU + SBC_BYTES;
#pragma unroll
        for (int ks = 0; ks < 2; ks++) {
            int kA = c * 32 + ks * 16;
            unsigned Ah[2][4], Al[2][4];
#pragma unroll
            for (int mi = 0; mi < 2; mi++) {
                unsigned aoff = (unsigned)((rb + mi * 16 + a_lr) * SA_STR + kA + a_lc) * 2;
                ldsm_x4(sAhiU + aoff, Ah[mi][0], Ah[mi][1], Ah[mi][2], Ah[mi][3]);
                ldsm_x4(sAloU + aoff, Al[mi][0], Al[mi][1], Al[mi][2], Al[mi][3]);
            }
#pragma unroll
            for (int np = 0; np < 4; np++) {
                unsigned boff = (unsigned)((wc * 64 + np * 16 + b_nr) * SBC_STR + ks * 16 + b_kc) * 2;
                unsigned Bh[4], Bl[4];
                ldsm_x4(sBhiU + boff, Bh[0], Bh[1], Bh[2], Bh[3]);
                ldsm_x4(sBloU + boff, Bl[0], Bl[1], Bl[2], Bl[3]);
#pragma unroll
                for (int mi = 0; mi < 2; mi++) {
#pragma unroll
                    for (int nj = 0; nj < 2; nj++) {
                        float* cc = acc[mi][np * 2 + nj];
                        mma16816(cc, Ah[mi], Bh[2 * nj], Bh[2 * nj + 1]);
                        mma16816(cc, Ah[mi], Bl[2 * nj], Bl[2 * nj + 1]);
                        mma16816(cc, Al[mi], Bh[2 * nj], Bh[2 * nj + 1]);
                    }
                }
            }
        }
        __syncthreads();
    }

    const int gid = lane >> 2, tig = lane & 3;
#pragma unroll
    for (int mi = 0; mi < 2; mi++) {
        int r0 = rb + mi * 16 + gid, r1 = r0 + 8;
#pragma unroll
        for (int nt = 0; nt < 8; nt++) {
            int C = wc * 64 + nt * 8 + tig * 2;
            float* cc = acc[mi][nt];
            *(float2*)(Cout + (row0 + r0) * 256 + C) = make_float2(cc[0], cc[1]);
            *(float2*)(Cout + (row0 + r1) * 256 + C) = make_float2(cc[2], cc[3]);
        }
    }
}

// ================= persistent recurrence kernel ============================
// CTA = (m = blockIdx.y, 64 b-rows at blockIdx.x*64). 256 threads (8 warps:
// 2 row-groups x 4 col-groups). State (bf16 hi/lo) + full U^T-hi resident in
// smem for all TT steps; only U^T-lo streams per step (1/3 of mma work).
__global__ __launch_bounds__(256, 1) void persist_kernel(const float* __restrict__ stories,
                                                         const float* __restrict__ mask,
                                                         const float* __restrict__ keys,
                                                         const float* __restrict__ V,
                                                         const float* __restrict__ prelu_a,
                                                         float* __restrict__ out) {
    extern __shared__ char sm[];
    __nv_bfloat16* sAhi = (__nv_bfloat16*)(sm + P_OFF_AHI);
    __nv_bfloat16* sAlo = (__nv_bfloat16*)(sm + P_OFF_ALO);
    __nv_bfloat16* sBh  = (__nv_bfloat16*)(sm + P_OFF_BH);
    __nv_bfloat16* sBl  = (__nv_bfloat16*)(sm + P_OFF_BL);
    float* sKeys = (float*)(sm + P_OFF_F32);
    float* sKC   = sKeys + 256;
    float* sPA   = sKC + 256;
    float* sGm   = sPA + 256;       // [64]
    float* sRS   = sGm + 64;        // [64][4]

    const int tid = threadIdx.x;
    const int lane = tid & 31, wid = tid >> 5;
    const int wr = wid >> 2, wc = wid & 3;
    const int rb = wr * 32;
    const int gid = lane >> 2, tig = lane & 3;
    const int m = blockIdx.y;
    const int b0 = blockIdx.x * 64;

    const int a_lr = ((lane >> 3) & 1) * 8 + (lane & 7);
    const int a_lc = ((lane >> 4) & 1) * 8;
    const int b_nr = ((lane >> 4) << 3) + (lane & 7);
    const int b_kc = ((lane >> 3) & 1) << 3;
    const unsigned sAhiU = smem_u32(sAhi), sAloU = smem_u32(sAlo);
    const unsigned sBhU = smem_u32(sBh), sBlU = smem_u32(sBl);

    float* __restrict__ gates_out = out + (size_t)MM * BB * HH;
    float* __restrict__ finmem = out;

    sKeys[tid] = keys[m * HH + tid];
    sPA[tid]   = prelu_a[tid];
    // keycand: kc[col] = sum_k keys[m,k] * V[k,col]
    {
        float p = 0.f;
        const float* vp = V + tid;
        const float* kp = keys + m * HH;
#pragma unroll 8
        for (int k = 0; k < 256; k++) p += kp[k] * vp[(size_t)k * HH];
        sKC[tid] = p;
    }
    // resident U^T hi: sBh[n][k], stride 264
    for (int i = tid; i < 256 * 32; i += 256) {
        int n = i >> 5, g = (i & 31) << 3;
        *(uint4*)(sBh + n * P_BH_STR + g) = *(const uint4*)(g_Uthi + n * 256 + g);
    }
    // init state rows = keys[m]
    for (int i = tid; i < 64 * 32; i += 256) {
        int row = i >> 5, kq = (i & 31) << 3;
        float4 v0 = *(const float4*)(keys + m * HH + kq);
        float4 v1 = *(const float4*)(keys + m * HH + kq + 4);
        uint4 h, l;
        split8(v0, v1, h, l);
        *(uint4*)(sAhi + row * P_SA_STR + kq) = h;
        *(uint4*)(sAlo + row * P_SA_STR + kq) = l;
    }
    __syncthreads();

    for (int t = 0; t < TT; t++) {
        // prefetch U^T-lo chunk 0 (hides under gate + resident slab 0)
        for (int i = tid; i < 1024; i += 256) {
            int n = i >> 2, g = (i & 3) << 3;
            cpasync16(sBlU + (unsigned)(n * P_BL_STR + g) * 2, g_Utlo + n * 256 + g);
        }
        asm volatile("cp.async.commit_group;");

        // ---- gate: sigmoid(dot(mem_row + keys, sent_row)) ----
        {
            int gr = tid >> 2, gq = tid & 3;
            const float* srow = stories + ((size_t)t * BB + b0 + gr) * HH + gq * 64;
            float p = 0.f;
#pragma unroll
            for (int kk = 0; kk < 64; kk += 2) {
                int k = gq * 64 + kk;
                __nv_bfloat162 h2 = *(__nv_bfloat162*)(sAhi + gr * P_SA_STR + k);
                __nv_bfloat162 l2 = *(__nv_bfloat162*)(sAlo + gr * P_SA_STR + k);
                float m0 = __bfloat162float(h2.x) + __bfloat162float(l2.x);
                float m1 = __bfloat162float(h2.y) + __bfloat162float(l2.y);
                p += (m0 + sKeys[k]) * srow[kk] + (m1 + sKeys[k + 1]) * srow[kk + 1];
            }
            p += __shfl_xor_sync(0xffffffffu, p, 1);
            p += __shfl_xor_sync(0xffffffffu, p, 2);
            if (gq == 0) {
                float g = 1.0f / (1.0f + expf(-p));
                gates_out[((size_t)t * MM + m) * BB + b0 + gr] = g;
                sGm[gr] = g * mask[t * BB + b0 + gr];
            }
        }

        // ---- mma: acc = state @ U  (AhBh + AlBh resident, AhBl streamed) ----
        float acc[2][8][4];
#pragma unroll
        for (int i = 0; i < 2; i++)
#pragma unroll
            for (int j = 0; j < 8; j++)
#pragma unroll
                for (int q = 0; q < 4; q++) acc[i][j][q] = 0.f;

        for (int c = 0; c < 8; c++) {
            unsigned AhS[2][2][4];          // saved A-hi frags [ks][mi]
            // resident slab: barrier-free
#pragma unroll
            for (int ks = 0; ks < 2; ks++) {
                int kcol = c * 32 + ks * 16;
                unsigned Al[2][4];
#pragma unroll
                for (int mi = 0; mi < 2; mi++) {
                    unsigned aoff = (unsigned)((rb + mi * 16 + a_lr) * P_SA_STR + kcol + a_lc) * 2;
                    ldsm_x4(sAhiU + aoff, AhS[ks][mi][0], AhS[ks][mi][1], AhS[ks][mi][2], AhS[ks][mi][3]);
                    ldsm_x4(sAloU + aoff, Al[mi][0], Al[mi][1], Al[mi][2], Al[mi][3]);
                }
#pragma unroll
                for (int np = 0; np < 4; np++) {
                    unsigned boff = (unsigned)((wc * 64 + np * 16 + b_nr) * P_BH_STR + kcol + b_kc) * 2;
                    unsigned Bh[4];
                    ldsm_x4(sBhU + boff, Bh[0], Bh[1], Bh[2], Bh[3]);
#pragma unroll
                    for (int mi = 0; mi < 2; mi++) {
#pragma unroll
                        for (int nj = 0; nj < 2; nj++) {
                            float* cc = acc[mi][np * 2 + nj];
                            mma16816(cc, AhS[ks][mi], Bh[2 * nj], Bh[2 * nj + 1]);
                            mma16816(cc, Al[mi], Bh[2 * nj], Bh[2 * nj + 1]);
                        }
                    }
                }
            }
            // streamed lo pass for this chunk
            asm volatile("cp.async.wait_group 0;");
            __syncthreads();
#pragma unroll
            for (int ks = 0; ks < 2; ks++) {
#pragma unroll
                for (int np = 0; np < 4; np++) {
                    unsigned boff = (unsigned)((wc * 64 + np * 16 + b_nr) * P_BL_STR + ks * 16 + b_kc) * 2;
                    unsigned Bl[4];
                    ldsm_x4(sBlU + boff, Bl[0], Bl[1], Bl[2], Bl[3]);
#pragma unroll
                    for (int mi = 0; mi < 2; mi++) {
#pragma unroll
                        for (int nj = 0; nj < 2; nj++)
                            mma16816(acc[mi][np * 2 + nj], AhS[ks][mi], Bl[2 * nj], Bl[2 * nj + 1]);
                    }
                }
            }
            __syncthreads();
            if (c < 7) {
                int kt = (c + 1) * 32;
                for (int i = tid; i < 1024; i += 256) {
                    int n = i >> 2, g = (i & 3) << 3;
                    cpasync16(sBlU + (unsigned)(n * P_BL_STR + g) * 2, g_Utlo + n * 256 + kt + g);
                }
                asm volatile("cp.async.commit_group;");
            }
        }

        // ---- epilogue: cand=prelu(acc+kc+sw); mem'=normalize(mem + g*m*cand) ----
        const float* __restrict__ swbase = g_sentW + ((size_t)t * BB + b0) * HH;
#pragma unroll
        for (int mi = 0; mi < 2; mi++) {
            int r0 = rb + mi * 16 + gid, r1 = r0 + 8;
            float gm0 = sGm[r0], gm1 = sGm[r1];
            float ss0 = 0.f, ss1 = 0.f;
#pragma unroll
            for (int nt = 0; nt < 8; nt++) {
                int C = wc * 64 + nt * 8 + tig * 2;
                float2 kc = *(const float2*)(sKC + C);
                float2 pa = *(const float2*)(sPA + C);
                float2 sw0 = *(const float2*)(swbase + (size_t)r0 * 256 + C);
                float2 sw1 = *(const float2*)(swbase + (size_t)r1 * 256 + C);
                __nv_bfloat162 h0 = *(__nv_bfloat162*)(sAhi + r0 * P_SA_STR + C);
                __nv_bfloat162 l0 = *(__nv_bfloat162*)(sAlo + r0 * P_SA_STR + C);
                __nv_bfloat162 h1 = *(__nv_bfloat162*)(sAhi + r1 * P_SA_STR + C);
                __nv_bfloat162 l1 = *(__nv_bfloat162*)(sAlo + r1 * P_SA_STR + C);
                float om0x = __bfloat162float(h0.x) + __bfloat162float(l0.x);
                float om0y = __bfloat162float(h0.y) + __bfloat162float(l0.y);
                float om1x = __bfloat162float(h1.x) + __bfloat162float(l1.x);
                float om1y = __bfloat162float(h1.y) + __bfloat162float(l1.y);
                float* cc = acc[mi][nt];
                float v;
                v = cc[0] + kc.x + sw0.x; v = (v >= 0.f) ? v : pa.x * v; v = om0x + gm0 * v; ss0 += v * v; cc[0] = v;
                v = cc[1] + kc.y + sw0.y; v = (v >= 0.f) ? v : pa.y * v; v = om0y + gm0 * v; ss0 += v * v; cc[1] = v;
                v = cc[2] + kc.x + sw1.x; v = (v >= 0.f) ? v : pa.x * v; v = om1x + gm1 * v; ss1 += v * v; cc[2] = v;
                v = cc[3] + kc.y + sw1.y; v = (v >= 0.f) ? v : pa.y * v; v = om1y + gm1 * v; ss1 += v * v; cc[3] = v;
            }
            ss0 += __shfl_xor_sync(0xffffffffu, ss0, 1);
            ss0 += __shfl_xor_sync(0xffffffffu, ss0, 2);
            ss1 += __shfl_xor_sync(0xffffffffu, ss1, 1);
            ss1 += __shfl_xor_sync(0xffffffffu, ss1, 2);
            if (tig == 0) {
                sRS[r0 * 4 + wc] = ss0;
                sRS[r1 * 4 + wc] = ss1;
            }
        }
        __syncthreads();

#pragma unroll
        for (int mi = 0; mi < 2; mi++) {
            int r0 = rb + mi * 16 + gid, r1 = r0 + 8;
            float s0 = sRS[r0 * 4 + 0] + sRS[r0 * 4 + 1] + sRS[r0 * 4 + 2] + sRS[r0 * 4 + 3];
            float s1 = sRS[r1 * 4 + 0] + sRS[r1 * 4 + 1] + sRS[r1 * 4 + 2] + sRS[r1 * 4 + 3];
            float sc0 = 1.0f / fmaxf(sqrtf(s0), 1e-12f);
            float sc1 = 1.0f / fmaxf(sqrtf(s1), 1e-12f);
#pragma unroll
            for (int nt = 0; nt < 8; nt++) {
                int C = wc * 64 + nt * 8 + tig * 2;
                float* cc = acc[mi][nt];
                float n0x = cc[0] * sc0, n0y = cc[1] * sc0;
                float n1x = cc[2] * sc1, n1y = cc[3] * sc1;
                __nv_bfloat16 h0x = __float2bfloat16(n0x), h0y = __float2bfloat16(n0y);
                __nv_bfloat16 h1x = __float2bfloat16(n1x), h1y = __float2bfloat16(n1y);
                __nv_bfloat16 l0x = __float2bfloat16(n0x - __bfloat162float(h0x));
                __nv_bfloat16 l0y = __float2bfloat16(n0y - __bfloat162float(h0y));
                __nv_bfloat16 l1x = __float2bfloat16(n1x - __bfloat162float(h1x));
                __nv_bfloat16 l1y = __float2bfloat16(n1y - __bfloat162float(h1y));
                *(unsigned*)(sAhi + r0 * P_SA_STR + C) = pack2(h0x, h0y);
                *(unsigned*)(sAlo + r0 * P_SA_STR + C) = pack2(l0x, l0y);
                *(unsigned*)(sAhi + r1 * P_SA_STR + C) = pack2(h1x, h1y);
                *(unsigned*)(sAlo + r1 * P_SA_STR + C) = pack2(l1x, l1y);
            }
        }
        __syncthreads();
    }

    // ---- final memory tile -> d_out ----
    for (int i = tid; i < 64 * 256; i += 256) {
        int row = i >> 8, col = i & 255;
        float v = __bfloat162float(sAhi[row * P_SA_STR + col]) + __bfloat162float(sAlo[row * P_SA_STR + col]);
        finmem[((size_t)m * BB + b0 + row) * HH + col] = v;
    }
}

// ---------------------------------------------------------------------------
extern "C" void kernel_launch(void* const* d_in, const int* in_sizes, int n_in,
                              void* d_out, int out_size) {
    const float* stories = (const float*)d_in[0];
    const float* mask    = (const float*)d_in[1];
    const float* keys    = (const float*)d_in[2];
    const float* U       = (const float*)d_in[3];
    const float* W       = (const float*)d_in[4];
    const float* V       = (const float*)d_in[5];
    const float* prelu_a = (const float*)d_in[6];
    float* out = (float*)d_out;

    static bool attr_done = false;
    if (!attr_done) {
        cudaFuncSetAttribute(tc_gemm_kernel, cudaFuncAttributeMaxDynamicSharedMemorySize, G_SMEM);
        cudaFuncSetAttribute(persist_kernel, cudaFuncAttributeMaxDynamicSharedMemorySize, P_SMEM);
        attr_done = true;
    }

    __nv_bfloat16 *uthi, *utlo, *wthi, *wtlo;
    cudaGetSymbolAddress((void**)&uthi, g_Uthi);
    cudaGetSymbolAddress((void**)&utlo, g_Utlo);
    cudaGetSymbolAddress((void**)&wthi, g_Wthi);
    cudaGetSymbolAddress((void**)&wtlo, g_Wtlo);
    float* sentw;
    cudaGetSymbolAddress((void**)&sentw, g_sentW);

    split_transpose_kernel<<<256, 256>>>(U, uthi, utlo);
    split_transpose_kernel<<<256, 256>>>(W, wthi, wtlo);

    // sentW[t,b,:] = stories[t,b,:] @ W for all t (one big GEMM)
    tc_gemm_kernel<<<(TT * BB) / 128, 512, G_SMEM>>>(stories, sentw);

    // whole recurrence in one persistent launch (state resident in smem)
    dim3 grid(BB / 64, MM);
    persist_kernel<<<grid, 256, P_SMEM>>>(stories, mask, keys, V, prelu_a, out);
}

// round 6
// speedup vs baseline: 1.0939x; 1.0054x over previous
#include <cuda_runtime.h>
#include <cuda_bf16.h>
#include <math.h>

#define TT 128
#define BB 512
#define HH 256
#define MM 64

// ---------------- device scratch (no allocation allowed) ----------------
__device__ float g_sentW[(size_t)TT * BB * HH];            // 64 MB: stories @ W
__device__ __nv_bfloat16 g_Uthi[HH * HH];                  // U^T hi  [n][k]
__device__ __nv_bfloat16 g_Utlo[HH * HH];                  // U^T lo
__device__ __nv_bfloat16 g_Wthi[HH * HH];                  // W^T hi
__device__ __nv_bfloat16 g_Wtlo[HH * HH];                  // W^T lo

// ================= tc_gemm (sentW precompute) smem layout (R3, unchanged) ==
#define SA_STR 264
#define SA_BYTES (128 * SA_STR * 2)
#define SBC_STR 40
#define SBC_BYTES (256 * SBC_STR * 2)
#define OFF_AHI 0
#define OFF_ALO SA_BYTES
#define OFF_B (2 * SA_BYTES)
#define OFF_F32 (OFF_B + 4 * SBC_BYTES)
#define G_SMEM (OFF_F32 + 1024)

// ================= persist kernel smem layout (64-row tile) ================
#define P_SA_STR 264
#define P_SA_SPLIT (64 * P_SA_STR * 2)         // 33792 B per split
#define P_OFF_AHI 0
#define P_OFF_ALO P_SA_SPLIT                   // 33792
#define P_OFF_BH  (2 * P_SA_SPLIT)             // 67584 ; resident U^T hi [256][264]
#define P_BH_STR 264
#define P_BH_BYTES (256 * P_BH_STR * 2)        // 135168
#define P_OFF_BL  (P_OFF_BH + P_BH_BYTES)      // 202752 ; streamed lo chunk [256][40]
#define P_BL_STR 40
#define P_BL_BYTES (256 * P_BL_STR * 2)        // 20480
#define P_OFF_F32 (P_OFF_BL + P_BL_BYTES)      // 223232
// f32 area: keys[256], kc[256], pa[256], gm[64], rs[256]
#define P_SMEM (P_OFF_F32 + (256 + 256 + 256 + 64 + 256) * 4)   // 227584

// ---------------- PTX helpers ----------------
__device__ __forceinline__ unsigned smem_u32(const void* p) {
    return (unsigned)__cvta_generic_to_shared(p);
}
__device__ __forceinline__ void ldsm_x4(unsigned addr, unsigned& r0, unsigned& r1, unsigned& r2, unsigned& r3) {
    asm volatile("ldmatrix.sync.aligned.m8n8.x4.shared.b16 {%0,%1,%2,%3}, [%4];"
                 : "=r"(r0), "=r"(r1), "=r"(r2), "=r"(r3) : "r"(addr));
}
__device__ __forceinline__ void mma16816(float* c, const unsigned* a, unsigned b0, unsigned b1) {
    asm volatile("mma.sync.aligned.m16n8k16.row.col.f32.bf16.bf16.f32 "
                 "{%0,%1,%2,%3}, {%4,%5,%6,%7}, {%8,%9}, {%0,%1,%2,%3};"
                 : "+f"(c[0]), "+f"(c[1]), "+f"(c[2]), "+f"(c[3])
                 : "r"(a[0]), "r"(a[1]), "r"(a[2]), "r"(a[3]), "r"(b0), "r"(b1));
}
__device__ __forceinline__ void cpasync16(unsigned dst, const void* src) {
    asm volatile("cp.async.cg.shared.global [%0], [%1], 16;" :: "r"(dst), "l"(src));
}
__device__ __forceinline__ unsigned pack2(__nv_bfloat16 a, __nv_bfloat16 b) {
    unsigned short ua = *reinterpret_cast<unsigned short*>(&a);
    unsigned short ub = *reinterpret_cast<unsigned short*>(&b);
    return (unsigned)ua | ((unsigned)ub << 16);
}
__device__ __forceinline__ void split8(float4 v0, float4 v1, uint4& h, uint4& l) {
    float f[8] = {v0.x, v0.y, v0.z, v0.w, v1.x, v1.y, v1.z, v1.w};
    unsigned hh[4], ll[4];
#pragma unroll
    for (int j = 0; j < 4; j++) {
        float a = f[2 * j], b = f[2 * j + 1];
        __nv_bfloat16 ha = __float2bfloat16(a), hb = __float2bfloat16(b);
        __nv_bfloat16 la = __float2bfloat16(a - __bfloat162float(ha));
        __nv_bfloat16 lb = __float2bfloat16(b - __bfloat162float(hb));
        hh[j] = pack2(ha, hb);
        ll[j] = pack2(la, lb);
    }
    h = make_uint4(hh[0], hh[1], hh[2], hh[3]);
    l = make_uint4(ll[0], ll[1], ll[2], ll[3]);
}

// ---------------- prep: transpose + hi/lo split of U, W ----------------
__global__ void split_transpose_kernel(const float* __restrict__ src,
                                       __nv_bfloat16* __restrict__ hi,
                                       __nv_bfloat16* __restrict__ lo) {
    int idx = blockIdx.x * 256 + threadIdx.x;
    int n = idx >> 8, k = idx & 255;
    float x = src[k * 256 + n];
    __nv_bfloat16 h = __float2bfloat16(x);
    hi[idx] = h;
    lo[idx] = __float2bfloat16(x - __bfloat162float(h));
}

// ================= tc_gemm machinery (R3, 128-row tiles) ===================
__device__ __forceinline__ void g_stage_A(const float* __restrict__ Asrc, char* sm, int tid) {
    __nv_bfloat16* sAhi = (__nv_bfloat16*)(sm + OFF_AHI);
    __nv_bfloat16* sAlo = (__nv_bfloat16*)(sm + OFF_ALO);
    for (int i = tid; i < 128 * 32; i += 512) {
        int row = i >> 5, kq = (i & 31) << 3;
        const float* p = Asrc + row * 256 + kq;
        float4 v0 = *(const float4*)p;
        float4 v1 = *(const float4*)(p + 4);
        uint4 h, l;
        split8(v0, v1, h, l);
        *(uint4*)(sAhi + row * SA_STR + kq) = h;
        *(uint4*)(sAlo + row * SA_STR + kq) = l;
    }
}
__device__ __forceinline__ void g_stage_B(char* sm, const __nv_bfloat16* __restrict__ Bthi,
                                          const __nv_bfloat16* __restrict__ Btlo,
                                          int buf, int kt, int tid) {
    __nv_bfloat16* bh = (__nv_bfloat16*)(sm + OFF_B + buf * 2 * SBC_BYTES);
    __nv_bfloat16* bl = (__nv_bfloat16*)(sm + OFF_B + buf * 2 * SBC_BYTES + SBC_BYTES);
    for (int i = tid; i < 1024; i += 512) {
        int n = i >> 2, g = (i & 3) << 3;
        cpasync16(smem_u32(bh + n * SBC_STR + g), Bthi + n * 256 + kt + g);
        cpasync16(smem_u32(bl + n * SBC_STR + g), Btlo + n * 256 + kt + g);
    }
}

__global__ __launch_bounds__(512, 1) void tc_gemm_kernel(const float* __restrict__ Asrc,
                                                         float* __restrict__ Cout) {
    extern __shared__ char sm[];
    const int tid = threadIdx.x;
    const int lane = tid & 31, wid = tid >> 5;
    const int wr = wid >> 2, wc = wid & 3;
    const int rb = wr * 32;
    const size_t row0 = (size_t)blockIdx.x * 128;
    const int a_lr = ((lane >> 3) & 1) * 8 + (lane & 7);
    const int a_lc = ((lane >> 4) & 1) * 8;
    const int b_nr = ((lane >> 4) << 3) + (lane & 7);
    const int b_kc = ((lane >> 3) & 1) << 3;
    const unsigned sAhiU = smem_u32(sm + OFF_AHI);
    const unsigned sAloU = smem_u32(sm + OFF_ALO);
    const unsigned sB0 = smem_u32(sm + OFF_B);

    g_stage_A(Asrc + row0 * 256, sm, tid);
    __syncthreads();

    float acc[2][8][4];
#pragma unroll
    for (int i = 0; i < 2; i++)
#pragma unroll
        for (int j = 0; j < 8; j++)
#pragma unroll
            for (int q = 0; q < 4; q++) acc[i][j][q] = 0.f;

    g_stage_B(sm, g_Wthi, g_Wtlo, 0, 0, tid);
    asm volatile("cp.async.commit_group;");

#pragma unroll 2
    for (int c = 0; c < 8; c++) {
        if (c < 7) {
            g_stage_B(sm, g_Wthi, g_Wtlo, (c + 1) & 1, (c + 1) * 32, tid);
            asm volatile("cp.async.commit_group;");
            asm volatile("cp.async.wait_group 1;");
        } else {
            asm volatile("cp.async.wait_group 0;");
        }
        __syncthreads();
        const unsigned sBhiU = sB0 + (c & 1) * 2 * SBC_BYTES;
        const unsigned sBloU = sBhiU + SBC_BYTES;
#pragma unroll
        for (int ks = 0; ks < 2; ks++) {
            int kA = c * 32 + ks * 16;
            unsigned Ah[2][4], Al[2][4];
#pragma unroll
            for (int mi = 0; mi < 2; mi++) {
                unsigned aoff = (unsigned)((rb + mi * 16 + a_lr) * SA_STR + kA + a_lc) * 2;
                ldsm_x4(sAhiU + aoff, Ah[mi][0], Ah[mi][1], Ah[mi][2], Ah[mi][3]);
                ldsm_x4(sAloU + aoff, Al[mi][0], Al[mi][1], Al[mi][2], Al[mi][3]);
            }
#pragma unroll
            for (int np = 0; np < 4; np++) {
                unsigned boff = (unsigned)((wc * 64 + np * 16 + b_nr) * SBC_STR + ks * 16 + b_kc) * 2;
                unsigned Bh[4], Bl[4];
                ldsm_x4(sBhiU + boff, Bh[0], Bh[1], Bh[2], Bh[3]);
                ldsm_x4(sBloU + boff, Bl[0], Bl[1], Bl[2], Bl[3]);
#pragma unroll
                for (int mi = 0; mi < 2; mi++) {
#pragma unroll
                    for (int nj = 0; nj < 2; nj++) {
                        float* cc = acc[mi][np * 2 + nj];
                        mma16816(cc, Ah[mi], Bh[2 * nj], Bh[2 * nj + 1]);
                        mma16816(cc, Ah[mi], Bl[2 * nj], Bl[2 * nj + 1]);
                        mma16816(cc, Al[mi], Bh[2 * nj], Bh[2 * nj + 1]);
                    }
                }
            }
        }
        __syncthreads();
    }

    const int gid = lane >> 2, tig = lane & 3;
#pragma unroll
    for (int mi = 0; mi < 2; mi++) {
        int r0 = rb + mi * 16 + gid, r1 = r0 + 8;
#pragma unroll
        for (int nt = 0; nt < 8; nt++) {
            int C = wc * 64 + nt * 8 + tig * 2;
            float* cc = acc[mi][nt];
            *(float2*)(Cout + (row0 + r0) * 256 + C) = make_float2(cc[0], cc[1]);
            *(float2*)(Cout + (row0 + r1) * 256 + C) = make_float2(cc[2], cc[3]);
        }
    }
}

// ================= persistent recurrence kernel ============================
// CTA = (m = blockIdx.y, 64 b-rows at blockIdx.x*64). 256 threads (8 warps:
// 2 row-groups x 4 col-groups). State (bf16 hi/lo) + full U^T-hi resident in
// smem for all TT steps; only U^T-lo streams per step (1/3 of mma work).
__global__ __launch_bounds__(256, 1) void persist_kernel(const float* __restrict__ stories,
                                                         const float* __restrict__ mask,
                                                         const float* __restrict__ keys,
                                                         const float* __restrict__ V,
                                                         const float* __restrict__ prelu_a,
                                                         float* __restrict__ out) {
    extern __shared__ char sm[];
    __nv_bfloat16* sAhi = (__nv_bfloat16*)(sm + P_OFF_AHI);
    __nv_bfloat16* sAlo = (__nv_bfloat16*)(sm + P_OFF_ALO);
    __nv_bfloat16* sBh  = (__nv_bfloat16*)(sm + P_OFF_BH);
    __nv_bfloat16* sBl  = (__nv_bfloat16*)(sm + P_OFF_BL);
    float* sKeys = (float*)(sm + P_OFF_F32);
    float* sKC   = sKeys + 256;
    float* sPA   = sKC + 256;
    float* sGm   = sPA + 256;       // [64]
    float* sRS   = sGm + 64;        // [64][4]

    const int tid = threadIdx.x;
    const int lane = tid & 31, wid = tid >> 5;
    const int wr = wid >> 2, wc = wid & 3;
    const int rb = wr * 32;
    const int gid = lane >> 2, tig = lane & 3;
    const int m = blockIdx.y;
    const int b0 = blockIdx.x * 64;

    const int a_lr = ((lane >> 3) & 1) * 8 + (lane & 7);
    const int a_lc = ((lane >> 4) & 1) * 8;
    const int b_nr = ((lane >> 4) << 3) + (lane & 7);
    const int b_kc = ((lane >> 3) & 1) << 3;
    const unsigned sAhiU = smem_u32(sAhi), sAloU = smem_u32(sAlo);
    const unsigned sBhU = smem_u32(sBh), sBlU = smem_u32(sBl);

    float* __restrict__ gates_out = out + (size_t)MM * BB * HH;
    float* __restrict__ finmem = out;

    sKeys[tid] = keys[m * HH + tid];
    sPA[tid]   = prelu_a[tid];
    // keycand: kc[col] = sum_k keys[m,k] * V[k,col]
    {
        float p = 0.f;
        const float* vp = V + tid;
        const float* kp = keys + m * HH;
#pragma unroll 8
        for (int k = 0; k < 256; k++) p += kp[k] * vp[(size_t)k * HH];
        sKC[tid] = p;
    }
    // resident U^T hi: sBh[n][k], stride 264
    for (int i = tid; i < 256 * 32; i += 256) {
        int n = i >> 5, g = (i & 31) << 3;
        *(uint4*)(sBh + n * P_BH_STR + g) = *(const uint4*)(g_Uthi + n * 256 + g);
    }
    // init state rows = keys[m]
    for (int i = tid; i < 64 * 32; i += 256) {
        int row = i >> 5, kq = (i & 31) << 3;
        float4 v0 = *(const float4*)(keys + m * HH + kq);
        float4 v1 = *(const float4*)(keys + m * HH + kq + 4);
        uint4 h, l;
        split8(v0, v1, h, l);
        *(uint4*)(sAhi + row * P_SA_STR + kq) = h;
        *(uint4*)(sAlo + row * P_SA_STR + kq) = l;
    }
    __syncthreads();

    for (int t = 0; t < TT; t++) {
        // prefetch U^T-lo chunk 0 (hides under gate + resident slab 0)
        for (int i = tid; i < 1024; i += 256) {
            int n = i >> 2, g = (i & 3) << 3;
            cpasync16(sBlU + (unsigned)(n * P_BL_STR + g) * 2, g_Utlo + n * 256 + g);
        }
        asm volatile("cp.async.commit_group;");

        // ---- gate: sigmoid(dot(mem_row + keys, sent_row)) ----
        {
            int gr = tid >> 2, gq = tid & 3;
            const float* srow = stories + ((size_t)t * BB + b0 + gr) * HH + gq * 64;
            float p = 0.f;
#pragma unroll
            for (int kk = 0; kk < 64; kk += 2) {
                int k = gq * 64 + kk;
                __nv_bfloat162 h2 = *(__nv_bfloat162*)(sAhi + gr * P_SA_STR + k);
                __nv_bfloat162 l2 = *(__nv_bfloat162*)(sAlo + gr * P_SA_STR + k);
                float m0 = __bfloat162float(h2.x) + __bfloat162float(l2.x);
                float m1 = __bfloat162float(h2.y) + __bfloat162float(l2.y);
                p += (m0 + sKeys[k]) * srow[kk] + (m1 + sKeys[k + 1]) * srow[kk + 1];
            }
            p += __shfl_xor_sync(0xffffffffu, p, 1);
            p += __shfl_xor_sync(0xffffffffu, p, 2);
            if (gq == 0) {
                float g = 1.0f / (1.0f + expf(-p));
                gates_out[((size_t)t * MM + m) * BB + b0 + gr] = g;
                sGm[gr] = g * mask[t * BB + b0 + gr];
            }
        }

        // ---- mma: acc = state @ U  (AhBh + AlBh resident, AhBl streamed) ----
        float acc[2][8][4];
#pragma unroll
        for (int i = 0; i < 2; i++)
#pragma unroll
            for (int j = 0; j < 8; j++)
#pragma unroll
                for (int q = 0; q < 4; q++) acc[i][j][q] = 0.f;

        for (int c = 0; c < 8; c++) {
            unsigned AhS[2][2][4];          // saved A-hi frags [ks][mi]
            // resident slab: barrier-free
#pragma unroll
            for (int ks = 0; ks < 2; ks++) {
                int kcol = c * 32 + ks * 16;
                unsigned Al[2][4];
#pragma unroll
                for (int mi = 0; mi < 2; mi++) {
                    unsigned aoff = (unsigned)((rb + mi * 16 + a_lr) * P_SA_STR + kcol + a_lc) * 2;
                    ldsm_x4(sAhiU + aoff, AhS[ks][mi][0], AhS[ks][mi][1], AhS[ks][mi][2], AhS[ks][mi][3]);
                    ldsm_x4(sAloU + aoff, Al[mi][0], Al[mi][1], Al[mi][2], Al[mi][3]);
                }
#pragma unroll
                for (int np = 0; np < 4; np++) {
                    unsigned boff = (unsigned)((wc * 64 + np * 16 + b_nr) * P_BH_STR + kcol + b_kc) * 2;
                    unsigned Bh[4];
                    ldsm_x4(sBhU + boff, Bh[0], Bh[1], Bh[2], Bh[3]);
#pragma unroll
                    for (int mi = 0; mi < 2; mi++) {
#pragma unroll
                        for (int nj = 0; nj < 2; nj++) {
                            float* cc = acc[mi][np * 2 + nj];
                            mma16816(cc, AhS[ks][mi], Bh[2 * nj], Bh[2 * nj + 1]);
                            mma16816(cc, Al[mi], Bh[2 * nj], Bh[2 * nj + 1]);
                        }
                    }
                }
            }
            // streamed lo pass for this chunk
            asm volatile("cp.async.wait_group 0;");
            __syncthreads();
#pragma unroll
            for (int ks = 0; ks < 2; ks++) {
#pragma unroll
                for (int np = 0; np < 4; np++) {
                    unsigned boff = (unsigned)((wc * 64 + np * 16 + b_nr) * P_BL_STR + ks * 16 + b_kc) * 2;
                    unsigned Bl[4];
                    ldsm_x4(sBlU + boff, Bl[0], Bl[1], Bl[2], Bl[3]);
#pragma unroll
                    for (int mi = 0; mi < 2; mi++) {
#pragma unroll
                        for (int nj = 0; nj < 2; nj++)
                            mma16816(acc[mi][np * 2 + nj], AhS[ks][mi], Bl[2 * nj], Bl[2 * nj + 1]);
                    }
                }
            }
            __syncthreads();
            if (c < 7) {
                int kt = (c + 1) * 32;
                for (int i = tid; i < 1024; i += 256) {
                    int n = i >> 2, g = (i & 3) << 3;
                    cpasync16(sBlU + (unsigned)(n * P_BL_STR + g) * 2, g_Utlo + n * 256 + kt + g);
                }
                asm volatile("cp.async.commit_group;");
            }
        }

        // ---- epilogue: cand=prelu(acc+kc+sw); mem'=normalize(mem + g*m*cand) ----
        const float* __restrict__ swbase = g_sentW + ((size_t)t * BB + b0) * HH;
#pragma unroll
        for (int mi = 0; mi < 2; mi++) {
            int r0 = rb + mi * 16 + gid, r1 = r0 + 8;
            float gm0 = sGm[r0], gm1 = sGm[r1];
            float ss0 = 0.f, ss1 = 0.f;
#pragma unroll
            for (int nt = 0; nt < 8; nt++) {
                int C = wc * 64 + nt * 8 + tig * 2;
                float2 kc = *(const float2*)(sKC + C);
                float2 pa = *(const float2*)(sPA + C);
                float2 sw0 = *(const float2*)(swbase + (size_t)r0 * 256 + C);
                float2 sw1 = *(const float2*)(swbase + (size_t)r1 * 256 + C);
                __nv_bfloat162 h0 = *(__nv_bfloat162*)(sAhi + r0 * P_SA_STR + C);
                __nv_bfloat162 l0 = *(__nv_bfloat162*)(sAlo + r0 * P_SA_STR + C);
                __nv_bfloat162 h1 = *(__nv_bfloat162*)(sAhi + r1 * P_SA_STR + C);
                __nv_bfloat162 l1 = *(__nv_bfloat162*)(sAlo + r1 * P_SA_STR + C);
                float om0x = __bfloat162float(h0.x) + __bfloat162float(l0.x);
                float om0y = __bfloat162float(h0.y) + __bfloat162float(l0.y);
                float om1x = __bfloat162float(h1.x) + __bfloat162float(l1.x);
                float om1y = __bfloat162float(h1.y) + __bfloat162float(l1.y);
                float* cc = acc[mi][nt];
                float v;
                v = cc[0] + kc.x + sw0.x; v = (v >= 0.f) ? v : pa.x * v; v = om0x + gm0 * v; ss0 += v * v; cc[0] = v;
                v = cc[1] + kc.y + sw0.y; v = (v >= 0.f) ? v : pa.y * v; v = om0y + gm0 * v; ss0 += v * v; cc[1] = v;
                v = cc[2] + kc.x + sw1.x; v = (v >= 0.f) ? v : pa.x * v; v = om1x + gm1 * v; ss1 += v * v; cc[2] = v;
                v = cc[3] + kc.y + sw1.y; v = (v >= 0.f) ? v : pa.y * v; v = om1y + gm1 * v; ss1 += v * v; cc[3] = v;
            }
            ss0 += __shfl_xor_sync(0xffffffffu, ss0, 1);
            ss0 += __shfl_xor_sync(0xffffffffu, ss0, 2);
            ss1 += __shfl_xor_sync(0xffffffffu, ss1, 1);
            ss1 += __shfl_xor_sync(0xffffffffu, ss1, 2);
            if (tig == 0) {
                sRS[r0 * 4 + wc] = ss0;
                sRS[r1 * 4 + wc] = ss1;
            }
        }
        __syncthreads();

#pragma unroll
        for (int mi = 0; mi < 2; mi++) {
            int r0 = rb + mi * 16 + gid, r1 = r0 + 8;
            float s0 = sRS[r0 * 4 + 0] + sRS[r0 * 4 + 1] + sRS[r0 * 4 + 2] + sRS[r0 * 4 + 3];
            float s1 = sRS[r1 * 4 + 0] + sRS[r1 * 4 + 1] + sRS[r1 * 4 + 2] + sRS[r1 * 4 + 3];
            float sc0 = 1.0f / fmaxf(sqrtf(s0), 1e-12f);
            float sc1 = 1.0f / fmaxf(sqrtf(s1), 1e-12f);
#pragma unroll
            for (int nt = 0; nt < 8; nt++) {
                int C = wc * 64 + nt * 8 + tig * 2;
                float* cc = acc[mi][nt];
                float n0x = cc[0] * sc0, n0y = cc[1] * sc0;
                float n1x = cc[2] * sc1, n1y = cc[3] * sc1;
                __nv_bfloat16 h0x = __float2bfloat16(n0x), h0y = __float2bfloat16(n0y);
                __nv_bfloat16 h1x = __float2bfloat16(n1x), h1y = __float2bfloat16(n1y);
                __nv_bfloat16 l0x = __float2bfloat16(n0x - __bfloat162float(h0x));
                __nv_bfloat16 l0y = __float2bfloat16(n0y - __bfloat162float(h0y));
                __nv_bfloat16 l1x = __float2bfloat16(n1x - __bfloat162float(h1x));
                __nv_bfloat16 l1y = __float2bfloat16(n1y - __bfloat162float(h1y));
                *(unsigned*)(sAhi + r0 * P_SA_STR + C) = pack2(h0x, h0y);
                *(unsigned*)(sAlo + r0 * P_SA_STR + C) = pack2(l0x, l0y);
                *(unsigned*)(sAhi + r1 * P_SA_STR + C) = pack2(h1x, h1y);
                *(unsigned*)(sAlo + r1 * P_SA_STR + C) = pack2(l1x, l1y);
            }
        }
        __syncthreads();
    }

    // ---- final memory tile -> d_out ----
    for (int i = tid; i < 64 * 256; i += 256) {
        int row = i >> 8, col = i & 255;
        float v = __bfloat162float(sAhi[row * P_SA_STR + col]) + __bfloat162float(sAlo[row * P_SA_STR + col]);
        finmem[((size_t)m * BB + b0 + row) * HH + col] = v;
    }
}

// ---------------------------------------------------------------------------
extern "C" void kernel_launch(void* const* d_in, const int* in_sizes, int n_in,
                              void* d_out, int out_size) {
    const float* stories = (const float*)d_in[0];
    const float* mask    = (const float*)d_in[1];
    const float* keys    = (const float*)d_in[2];
    const float* U       = (const float*)d_in[3];
    const float* W       = (const float*)d_in[4];
    const float* V       = (const float*)d_in[5];
    const float* prelu_a = (const float*)d_in[6];
    float* out = (float*)d_out;

    static bool attr_done = false;
    if (!attr_done) {
        cudaFuncSetAttribute(tc_gemm_kernel, cudaFuncAttributeMaxDynamicSharedMemorySize, G_SMEM);
        cudaFuncSetAttribute(persist_kernel, cudaFuncAttributeMaxDynamicSharedMemorySize, P_SMEM);
        attr_done = true;
    }

    __nv_bfloat16 *uthi, *utlo, *wthi, *wtlo;
    cudaGetSymbolAddress((void**)&uthi, g_Uthi);
    cudaGetSymbolAddress((void**)&utlo, g_Utlo);
    cudaGetSymbolAddress((void**)&wthi, g_Wthi);
    cudaGetSymbolAddress((void**)&wtlo, g_Wtlo);
    float* sentw;
    cudaGetSymbolAddress((void**)&sentw, g_sentW);

    split_transpose_kernel<<<256, 256>>>(U, uthi, utlo);
    split_transpose_kernel<<<256, 256>>>(W, wthi, wtlo);

    // sentW[t,b,:] = stories[t,b,:] @ W for all t (one big GEMM)
    tc_gemm_kernel<<<(TT * BB) / 128, 512, G_SMEM>>>(stories, sentw);

    // whole recurrence in one persistent launch (state resident in smem)
    dim3 grid(BB / 64, MM);
    persist_kernel<<<grid, 256, P_SMEM>>>(stories, mask, keys, V, prelu_a, out);
}

// round 10
// speedup vs baseline: 1.7272x; 1.5790x over previous
#include <cuda_runtime.h>
#include <cuda_fp16.h>
#include <cuda_bf16.h>
#include <math.h>
#include <stdint.h>

#define TT 128
#define BB 512
#define HH 256
#define MM 64

__device__ float g_sentW[(size_t)TT * BB * HH];   // stories @ W (fp32)
__device__ __half g_Uth[HH * HH];                  // U^T fp16 [n][k]
__device__ __nv_bfloat16 g_Wthi[HH * HH];          // W^T hi/lo for sentW precompute
__device__ __nv_bfloat16 g_Wtlo[HH * HH];

// ---------------- helpers ----------------
__device__ __forceinline__ unsigned smem_u32(const void* p) {
    return (unsigned)__cvta_generic_to_shared(p);
}
__device__ __forceinline__ void ldsm_x4(unsigned addr, unsigned& r0, unsigned& r1, unsigned& r2, unsigned& r3) {
    asm volatile("ldmatrix.sync.aligned.m8n8.x4.shared.b16 {%0,%1,%2,%3}, [%4];"
                 : "=r"(r0), "=r"(r1), "=r"(r2), "=r"(r3) : "r"(addr));
}
__device__ __forceinline__ void mma_bf16(float* c, const unsigned* a, unsigned b0, unsigned b1) {
    asm volatile("mma.sync.aligned.m16n8k16.row.col.f32.bf16.bf16.f32 "
                 "{%0,%1,%2,%3}, {%4,%5,%6,%7}, {%8,%9}, {%0,%1,%2,%3};"
                 : "+f"(c[0]), "+f"(c[1]), "+f"(c[2]), "+f"(c[3])
                 : "r"(a[0]), "r"(a[1]), "r"(a[2]), "r"(a[3]), "r"(b0), "r"(b1));
}
__device__ __forceinline__ void mma_f16(float* c, const unsigned* a, unsigned b0, unsigned b1) {
    asm volatile("mma.sync.aligned.m16n8k16.row.col.f32.f16.f16.f32 "
                 "{%0,%1,%2,%3}, {%4,%5,%6,%7}, {%8,%9}, {%0,%1,%2,%3};"
                 : "+f"(c[0]), "+f"(c[1]), "+f"(c[2]), "+f"(c[3])
                 : "r"(a[0]), "r"(a[1]), "r"(a[2]), "r"(a[3]), "r"(b0), "r"(b1));
}
__device__ __forceinline__ void cpasync16(unsigned dst, const void* src) {
    asm volatile("cp.async.cg.shared.global [%0], [%1], 16;" :: "r"(dst), "l"(src));
}
__device__ __forceinline__ unsigned pack2bf(__nv_bfloat16 a, __nv_bfloat16 b) {
    unsigned short ua = *reinterpret_cast<unsigned short*>(&a);
    unsigned short ub = *reinterpret_cast<unsigned short*>(&b);
    return (unsigned)ua | ((unsigned)ub << 16);
}
__device__ __forceinline__ uint32_t h2u(__half2 v) {
    union { __half2 h; uint32_t u; } c; c.h = v; return c.u;
}
__device__ __forceinline__ __half2 u2h(uint32_t v) {
    union { __half2 h; uint32_t u; } c; c.u = v; return c.h;
}
__device__ __forceinline__ void split8(float4 v0, float4 v1, uint4& h, uint4& l) {
    float f[8] = {v0.x, v0.y, v0.z, v0.w, v1.x, v1.y, v1.z, v1.w};
    unsigned hh[4], ll[4];
#pragma unroll
    for (int j = 0; j < 4; j++) {
        float a = f[2 * j], b = f[2 * j + 1];
        __nv_bfloat16 ha = __float2bfloat16(a), hb = __float2bfloat16(b);
        __nv_bfloat16 la = __float2bfloat16(a - __bfloat162float(ha));
        __nv_bfloat16 lb = __float2bfloat16(b - __bfloat162float(hb));
        hh[j] = pack2bf(ha, hb); ll[j] = pack2bf(la, lb);
    }
    h = make_uint4(hh[0], hh[1], hh[2], hh[3]);
    l = make_uint4(ll[0], ll[1], ll[2], ll[3]);
}

// ---------------- prep ----------------
__global__ void split_transpose_kernel(const float* __restrict__ src,
                                       __nv_bfloat16* __restrict__ hi,
                                       __nv_bfloat16* __restrict__ lo) {
    int idx = blockIdx.x * 256 + threadIdx.x;
    int n = idx >> 8, k = idx & 255;
    float x = src[k * 256 + n];
    __nv_bfloat16 h = __float2bfloat16(x);
    hi[idx] = h;
    lo[idx] = __float2bfloat16(x - __bfloat162float(h));
}
__global__ void prep_Uth_kernel(const float* __restrict__ U) {
    int idx = blockIdx.x * 256 + threadIdx.x;
    int n = idx >> 8, k = idx & 255;
    g_Uth[idx] = __float2half(U[k * 256 + n]);
}

// ---------------- sentW precompute (bf16 3-pass, fp32 out; from R3) -------
#define SA_STR 264
#define SA_BYTES (128 * SA_STR * 2)
#define SBC_STR 40
#define SBC_BYTES (256 * SBC_STR * 2)
#define OFF_AHI 0
#define OFF_ALO SA_BYTES
#define OFF_B (2 * SA_BYTES)
#define G_SMEM (OFF_B + 4 * SBC_BYTES + 1024)

__device__ __forceinline__ void g_stage_A(const float* __restrict__ Asrc, char* sm, int tid) {
    __nv_bfloat16* sAhi = (__nv_bfloat16*)(sm + OFF_AHI);
    __nv_bfloat16* sAlo = (__nv_bfloat16*)(sm + OFF_ALO);
    for (int i = tid; i < 128 * 32; i += 512) {
        int row = i >> 5, kq = (i & 31) << 3;
        const float* p = Asrc + row * 256 + kq;
        float4 v0 = *(const float4*)p;
        float4 v1 = *(const float4*)(p + 4);
        uint4 h, l;
        split8(v0, v1, h, l);
        *(uint4*)(sAhi + row * SA_STR + kq) = h;
        *(uint4*)(sAlo + row * SA_STR + kq) = l;
    }
}
__device__ __forceinline__ void g_stage_B(char* sm, const __nv_bfloat16* __restrict__ Bthi,
                                          const __nv_bfloat16* __restrict__ Btlo,
                                          int buf, int kt, int tid) {
    __nv_bfloat16* bh = (__nv_bfloat16*)(sm + OFF_B + buf * 2 * SBC_BYTES);
    __nv_bfloat16* bl = (__nv_bfloat16*)(sm + OFF_B + buf * 2 * SBC_BYTES + SBC_BYTES);
    for (int i = tid; i < 1024; i += 512) {
        int n = i >> 2, g = (i & 3) << 3;
        cpasync16(smem_u32(bh + n * SBC_STR + g), Bthi + n * 256 + kt + g);
        cpasync16(smem_u32(bl + n * SBC_STR + g), Btlo + n * 256 + kt + g);
    }
}

__global__ __launch_bounds__(512, 1) void tc_gemm_kernel(const float* __restrict__ Asrc,
                                                         float* __restrict__ Cout) {
    extern __shared__ char sm[];
    const int tid = threadIdx.x;
    const int lane = tid & 31, wid = tid >> 5;
    const int wr = wid >> 2, wc = wid & 3;
    const int rb = wr * 32;
    const size_t row0 = (size_t)blockIdx.x * 128;
    const int a_lr = ((lane >> 3) & 1) * 8 + (lane & 7);
    const int a_lc = ((lane >> 4) & 1) * 8;
    const int b_nr = ((lane >> 4) << 3) + (lane & 7);
    const int b_kc = ((lane >> 3) & 1) << 3;
    const unsigned sAhiU = smem_u32(sm + OFF_AHI);
    const unsigned sAloU = smem_u32(sm + OFF_ALO);
    const unsigned sB0 = smem_u32(sm + OFF_B);

    g_stage_A(Asrc + row0 * 256, sm, tid);
    __syncthreads();

    float acc[2][8][4];
#pragma unroll
    for (int i = 0; i < 2; i++)
#pragma unroll
        for (int j = 0; j < 8; j++)
#pragma unroll
            for (int q = 0; q < 4; q++) acc[i][j][q] = 0.f;

    g_stage_B(sm, g_Wthi, g_Wtlo, 0, 0, tid);
    asm volatile("cp.async.commit_group;");

#pragma unroll 2
    for (int c = 0; c < 8; c++) {
        if (c < 7) {
            g_stage_B(sm, g_Wthi, g_Wtlo, (c + 1) & 1, (c + 1) * 32, tid);
            asm volatile("cp.async.commit_group;");
            asm volatile("cp.async.wait_group 1;");
        } else {
            asm volatile("cp.async.wait_group 0;");
        }
        __syncthreads();
        const unsigned sBhiU = sB0 + (c & 1) * 2 * SBC_BYTES;
        const unsigned sBloU = sBhiU + SBC_BYTES;
#pragma unroll
        for (int ks = 0; ks < 2; ks++) {
            int kA = c * 32 + ks * 16;
            unsigned Ah[2][4], Al[2][4];
#pragma unroll
            for (int mi = 0; mi < 2; mi++) {
                unsigned aoff = (unsigned)((rb + mi * 16 + a_lr) * SA_STR + kA + a_lc) * 2;
                ldsm_x4(sAhiU + aoff, Ah[mi][0], Ah[mi][1], Ah[mi][2], Ah[mi][3]);
                ldsm_x4(sAloU + aoff, Al[mi][0], Al[mi][1], Al[mi][2], Al[mi][3]);
            }
#pragma unroll
            for (int np = 0; np < 4; np++) {
                unsigned boff = (unsigned)((wc * 64 + np * 16 + b_nr) * SBC_STR + ks * 16 + b_kc) * 2;
                unsigned Bh[4], Bl[4];
                ldsm_x4(sBhiU + boff, Bh[0], Bh[1], Bh[2], Bh[3]);
                ldsm_x4(sBloU + boff, Bl[0], Bl[1], Bl[2], Bl[3]);
#pragma unroll
                for (int mi = 0; mi < 2; mi++) {
#pragma unroll
                    for (int nj = 0; nj < 2; nj++) {
                        float* cc = acc[mi][np * 2 + nj];
                        mma_bf16(cc, Ah[mi], Bh[2 * nj], Bh[2 * nj + 1]);
                        mma_bf16(cc, Ah[mi], Bl[2 * nj], Bl[2 * nj + 1]);
                        mma_bf16(cc, Al[mi], Bh[2 * nj], Bh[2 * nj + 1]);
                    }
                }
            }
        }
        __syncthreads();
    }

    const int gid = lane >> 2, tig = lane & 3;
#pragma unroll
    for (int mi = 0; mi < 2; mi++) {
        int r0 = rb + mi * 16 + gid, r1 = r0 + 8;
#pragma unroll
        for (int nt = 0; nt < 8; nt++) {
            int C = wc * 64 + nt * 8 + tig * 2;
            float* cc = acc[mi][nt];
            *(float2*)(Cout + (row0 + r0) * 256 + C) = make_float2(cc[0], cc[1]);
            *(float2*)(Cout + (row0 + r1) * 256 + C) = make_float2(cc[2], cc[3]);
        }
    }
}

// ================= persistent recurrence: single-pass fp16 =================
// CTA = (m, 64 b-rows). 256 threads, 8 warps (2 row-groups x 4 col-groups).
// State fp16 [64][264] + FULL U^T fp16 [256][264] resident in smem.
// mma core: barrier-free, single pass, 16 k-steps.
#define P_SA_STR 264
#define P_SA_BYTES (64 * P_SA_STR * 2)         // 33792
#define P_BH_STR 264
#define P_BH_BYTES (256 * P_BH_STR * 2)        // 135168
#define P_OFF_A 0
#define P_OFF_B P_SA_BYTES
#define P_OFF_F32 (P_OFF_B + P_BH_BYTES)       // 168960
// f32: keys[256], kc[256], pa[256], gm[64], rs[256]
#define P_SMEM (P_OFF_F32 + (256 + 256 + 256 + 64 + 256) * 4)   // 173184

__global__ __launch_bounds__(256, 1) void persist_kernel(const float* __restrict__ stories,
                                                         const float* __restrict__ mask,
                                                         const float* __restrict__ keys,
                                                         const float* __restrict__ V,
                                                         const float* __restrict__ prelu_a,
                                                         float* __restrict__ out) {
    extern __shared__ char sm[];
    __half* sA = (__half*)(sm + P_OFF_A);
    __half* sB = (__half*)(sm + P_OFF_B);
    float* sKeys = (float*)(sm + P_OFF_F32);
    float* sKC   = sKeys + 256;
    float* sPA   = sKC + 256;
    float* sGm   = sPA + 256;      // [64]
    float* sRS   = sGm + 64;       // [64][4]

    const int tid = threadIdx.x;
    const int lane = tid & 31, wid = tid >> 5;
    const int wr = wid >> 2, wc = wid & 3;
    const int rb = wr * 32;
    const int gid = lane >> 2, tig = lane & 3;
    const int m = blockIdx.y;
    const int b0 = blockIdx.x * 64;

    const int a_lr = ((lane >> 3) & 1) * 8 + (lane & 7);
    const int a_lc = ((lane >> 4) & 1) * 8;
    const int b_nr = ((lane >> 4) << 3) + (lane & 7);
    const int b_kc = ((lane >> 3) & 1) << 3;
    const unsigned sAU = smem_u32(sA), sBU = smem_u32(sB);

    float* __restrict__ gates_out = out + (size_t)MM * BB * HH;

    sKeys[tid] = keys[m * HH + tid];
    sPA[tid]   = prelu_a[tid];
    // keycand: kc[col] = sum_k keys[m,k] * V[k,col]
    {
        float p = 0.f;
        const float* vp = V + tid;
        const float* kp = keys + m * HH;
#pragma unroll 8
        for (int k = 0; k < 256; k++) p += kp[k] * vp[(size_t)k * HH];
        sKC[tid] = p;
    }
    // resident U^T fp16
    for (int i = tid; i < 256 * 32; i += 256) {
        int n = i >> 5, g = (i & 31) << 3;
        float4 v0 = *(const float4*)((const void*)0); (void)v0; // placeholder removed below
    }
    // (real U load: 8 halves per iter from g_Uth)
    for (int i = tid; i < 256 * 32; i += 256) {
        int n = i >> 5, g = (i & 31) << 3;
        *(uint4*)(sB + n * P_BH_STR + g) = *(const uint4*)(g_Uth + n * 256 + g);
    }
    // init state rows = keys[m]
    for (int i = tid; i < 64 * 32; i += 256) {
        int row = i >> 5, kq = (i & 31) << 3;
#pragma unroll
        for (int j = 0; j < 4; j++) {
            float2 kv = *(const float2*)(keys + m * HH + kq + 2 * j);
            *(uint32_t*)(sA + row * P_SA_STR + kq + 2 * j) = h2u(__float22half2_rn(kv));
        }
    }
    __syncthreads();

    for (int t = 0; t < TT; t++) {
        // ---- mma: acc = state @ U (single-pass fp16, barrier-free) ----
        float acc[2][8][4];
#pragma unroll
        for (int i = 0; i < 2; i++)
#pragma unroll
            for (int j = 0; j < 8; j++)
#pragma unroll
                for (int q = 0; q < 4; q++) acc[i][j][q] = 0.f;

#pragma unroll 4
        for (int ks = 0; ks < 16; ks++) {
            int kcol = ks * 16;
            unsigned Af[2][4];
#pragma unroll
            for (int mi = 0; mi < 2; mi++) {
                unsigned aoff = (unsigned)((rb + mi * 16 + a_lr) * P_SA_STR + kcol + a_lc) * 2;
                ldsm_x4(sAU + aoff, Af[mi][0], Af[mi][1], Af[mi][2], Af[mi][3]);
            }
#pragma unroll
            for (int np = 0; np < 4; np++) {
                unsigned boff = (unsigned)((wc * 64 + np * 16 + b_nr) * P_BH_STR + kcol + b_kc) * 2;
                unsigned Bf[4];
                ldsm_x4(sBU + boff, Bf[0], Bf[1], Bf[2], Bf[3]);
#pragma unroll
                for (int mi = 0; mi < 2; mi++) {
#pragma unroll
                    for (int nj = 0; nj < 2; nj++)
                        mma_f16(acc[mi][np * 2 + nj], Af[mi], Bf[2 * nj], Bf[2 * nj + 1]);
                }
            }
        }

        // ---- gate: sigmoid(dot(mem_row + keys, sent_row)) ----
        {
            int gr = tid >> 2, gq = tid & 3;
            const float* srow = stories + ((size_t)t * BB + b0 + gr) * HH + gq * 64;
            float p = 0.f;
#pragma unroll
            for (int kk = 0; kk < 64; kk += 2) {
                int k = gq * 64 + kk;
                float2 a2 = __half22float2(u2h(*(const uint32_t*)(sA + gr * P_SA_STR + k)));
                p += (a2.x + sKeys[k]) * srow[kk] + (a2.y + sKeys[k + 1]) * srow[kk + 1];
            }
            p += __shfl_xor_sync(0xffffffffu, p, 1);
            p += __shfl_xor_sync(0xffffffffu, p, 2);
            if (gq == 0) {
                float g = 1.0f / (1.0f + expf(-p));
                gates_out[((size_t)t * MM + m) * BB + b0 + gr] = g;
                sGm[gr] = g * mask[t * BB + b0 + gr];
            }
        }
        __syncthreads();

        // ---- epilogue: cand = prelu(acc+kc+sw); n = old + gm*cand ----
        const float* __restrict__ swbase = g_sentW + ((size_t)t * BB + b0) * HH;
#pragma unroll
        for (int mi = 0; mi < 2; mi++) {
            int r0 = rb + mi * 16 + gid, r1 = r0 + 8;
            float gm0 = sGm[r0], gm1 = sGm[r1];
            float ss0 = 0.f, ss1 = 0.f;
#pragma unroll
            for (int nt = 0; nt < 8; nt++) {
                int C = wc * 64 + nt * 8 + tig * 2;
                float2 kc = *(const float2*)(sKC + C);
                float2 pa = *(const float2*)(sPA + C);
                float2 sw0 = *(const float2*)(swbase + (size_t)r0 * 256 + C);
                float2 sw1 = *(const float2*)(swbase + (size_t)r1 * 256 + C);
                float2 o0 = __half22float2(u2h(*(const uint32_t*)(sA + r0 * P_SA_STR + C)));
                float2 o1 = __half22float2(u2h(*(const uint32_t*)(sA + r1 * P_SA_STR + C)));
                float* cc = acc[mi][nt];
                float v;
                v = cc[0] + kc.x + sw0.x; v = (v >= 0.f) ? v : pa.x * v; v = o0.x + gm0 * v; ss0 += v * v; cc[0] = v;
                v = cc[1] + kc.y + sw0.y; v = (v >= 0.f) ? v : pa.y * v; v = o0.y + gm0 * v; ss0 += v * v; cc[1] = v;
                v = cc[2] + kc.x + sw1.x; v = (v >= 0.f) ? v : pa.x * v; v = o1.x + gm1 * v; ss1 += v * v; cc[2] = v;
                v = cc[3] + kc.y + sw1.y; v = (v >= 0.f) ? v : pa.y * v; v = o1.y + gm1 * v; ss1 += v * v; cc[3] = v;
            }
            ss0 += __shfl_xor_sync(0xffffffffu, ss0, 1);
            ss0 += __shfl_xor_sync(0xffffffffu, ss0, 2);
            ss1 += __shfl_xor_sync(0xffffffffu, ss1, 1);
            ss1 += __shfl_xor_sync(0xffffffffu, ss1, 2);
            if (tig == 0) {
                sRS[r0 * 4 + wc] = ss0;
                sRS[r1 * 4 + wc] = ss1;
            }
        }
        __syncthreads();

        const bool last = (t == TT - 1);
#pragma unroll
        for (int mi = 0; mi < 2; mi++) {
            int r0 = rb + mi * 16 + gid, r1 = r0 + 8;
            float s0 = sRS[r0 * 4 + 0] + sRS[r0 * 4 + 1] + sRS[r0 * 4 + 2] + sRS[r0 * 4 + 3];
            float s1 = sRS[r1 * 4 + 0] + sRS[r1 * 4 + 1] + sRS[r1 * 4 + 2] + sRS[r1 * 4 + 3];
            float sc0 = 1.0f / fmaxf(sqrtf(s0), 1e-12f);
            float sc1 = 1.0f / fmaxf(sqrtf(s1), 1e-12f);
#pragma unroll
            for (int nt = 0; nt < 8; nt++) {
                int C = wc * 64 + nt * 8 + tig * 2;
                float* cc = acc[mi][nt];
                float n0x = cc[0] * sc0, n0y = cc[1] * sc0;
                float n1x = cc[2] * sc1, n1y = cc[3] * sc1;
                *(uint32_t*)(sA + r0 * P_SA_STR + C) = h2u(__float22half2_rn(make_float2(n0x, n0y)));
                *(uint32_t*)(sA + r1 * P_SA_STR + C) = h2u(__float22half2_rn(make_float2(n1x, n1y)));
                if (last) {
                    *(float2*)(out + ((size_t)m * BB + b0 + r0) * HH + C) = make_float2(n0x, n0y);
                    *(float2*)(out + ((size_t)m * BB + b0 + r1) * HH + C) = make_float2(n1x, n1y);
                }
            }
        }
        __syncthreads();
    }
}

// ---------------------------------------------------------------------------
extern "C" void kernel_launch(void* const* d_in, const int* in_sizes, int n_in,
                              void* d_out, int out_size) {
    const float* stories = (const float*)d_in[0];
    const float* mask    = (const float*)d_in[1];
    const float* keys    = (const float*)d_in[2];
    const float* U       = (const float*)d_in[3];
    const float* W       = (const float*)d_in[4];
    const float* V       = (const float*)d_in[5];
    const float* prelu_a = (const float*)d_in[6];
    float* out = (float*)d_out;

    static bool attr_done = false;
    if (!attr_done) {
        cudaFuncSetAttribute(tc_gemm_kernel,  cudaFuncAttributeMaxDynamicSharedMemorySize, G_SMEM);
        cudaFuncSetAttribute(persist_kernel,  cudaFuncAttributeMaxDynamicSharedMemorySize, P_SMEM);
        attr_done = true;
    }

    __nv_bfloat16 *wthi, *wtlo;
    cudaGetSymbolAddress((void**)&wthi, g_Wthi);
    cudaGetSymbolAddress((void**)&wtlo, g_Wtlo);
    float* sentw;
    cudaGetSymbolAddress((void**)&sentw, g_sentW);

    split_transpose_kernel<<<256, 256>>>(W, wthi, wtlo);
    prep_Uth_kernel<<<256, 256>>>(U);
    tc_gemm_kernel<<<(TT * BB) / 128, 512, G_SMEM>>>(stories, sentw);

    dim3 grid(BB / 64, MM);
    persist_kernel<<<grid, 256, P_SMEM>>>(stories, mask, keys, V, prelu_a, out);
}

// round 11
// speedup vs baseline: 4.1949x; 2.4288x over previous
#include <cuda_runtime.h>
#include <cuda_fp16.h>
#include <cuda_bf16.h>
#include <math.h>
#include <stdint.h>

#define TT 128
#define BB 512
#define HH 256
#define MM 64

__device__ __half g_sentWh[(size_t)TT * BB * HH];  // stories @ W (fp16)
__device__ __half g_storiesh[(size_t)TT * BB * HH]; // stories (fp16)
__device__ __half g_Uth[HH * HH];                   // U^T fp16 [n][k]
__device__ __nv_bfloat16 g_Wthi[HH * HH];
__device__ __nv_bfloat16 g_Wtlo[HH * HH];

// ---------------- helpers ----------------
__device__ __forceinline__ unsigned smem_u32(const void* p) {
    return (unsigned)__cvta_generic_to_shared(p);
}
__device__ __forceinline__ void ldsm_x4(unsigned addr, unsigned& r0, unsigned& r1, unsigned& r2, unsigned& r3) {
    asm volatile("ldmatrix.sync.aligned.m8n8.x4.shared.b16 {%0,%1,%2,%3}, [%4];"
                 : "=r"(r0), "=r"(r1), "=r"(r2), "=r"(r3) : "r"(addr));
}
__device__ __forceinline__ void mma_bf16(float* c, const unsigned* a, unsigned b0, unsigned b1) {
    asm volatile("mma.sync.aligned.m16n8k16.row.col.f32.bf16.bf16.f32 "
                 "{%0,%1,%2,%3}, {%4,%5,%6,%7}, {%8,%9}, {%0,%1,%2,%3};"
                 : "+f"(c[0]), "+f"(c[1]), "+f"(c[2]), "+f"(c[3])
                 : "r"(a[0]), "r"(a[1]), "r"(a[2]), "r"(a[3]), "r"(b0), "r"(b1));
}
__device__ __forceinline__ void mma_f16(float* c, const unsigned* a, unsigned b0, unsigned b1) {
    asm volatile("mma.sync.aligned.m16n8k16.row.col.f32.f16.f16.f32 "
                 "{%0,%1,%2,%3}, {%4,%5,%6,%7}, {%8,%9}, {%0,%1,%2,%3};"
                 : "+f"(c[0]), "+f"(c[1]), "+f"(c[2]), "+f"(c[3])
                 : "r"(a[0]), "r"(a[1]), "r"(a[2]), "r"(a[3]), "r"(b0), "r"(b1));
}
__device__ __forceinline__ void cpasync16(unsigned dst, const void* src) {
    asm volatile("cp.async.cg.shared.global [%0], [%1], 16;" :: "r"(dst), "l"(src));
}
__device__ __forceinline__ unsigned pack2bf(__nv_bfloat16 a, __nv_bfloat16 b) {
    unsigned short ua = *reinterpret_cast<unsigned short*>(&a);
    unsigned short ub = *reinterpret_cast<unsigned short*>(&b);
    return (unsigned)ua | ((unsigned)ub << 16);
}
__device__ __forceinline__ uint32_t h2u(__half2 v) {
    union { __half2 h; uint32_t u; } c; c.h = v; return c.u;
}
__device__ __forceinline__ __half2 u2h(uint32_t v) {
    union { __half2 h; uint32_t u; } c; c.u = v; return c.h;
}
__device__ __forceinline__ void split8(float4 v0, float4 v1, uint4& h, uint4& l) {
    float f[8] = {v0.x, v0.y, v0.z, v0.w, v1.x, v1.y, v1.z, v1.w};
    unsigned hh[4], ll[4];
#pragma unroll
    for (int j = 0; j < 4; j++) {
        float a = f[2 * j], b = f[2 * j + 1];
        __nv_bfloat16 ha = __float2bfloat16(a), hb = __float2bfloat16(b);
        __nv_bfloat16 la = __float2bfloat16(a - __bfloat162float(ha));
        __nv_bfloat16 lb = __float2bfloat16(b - __bfloat162float(hb));
        hh[j] = pack2bf(ha, hb); ll[j] = pack2bf(la, lb);
    }
    h = make_uint4(hh[0], hh[1], hh[2], hh[3]);
    l = make_uint4(ll[0], ll[1], ll[2], ll[3]);
}

// ---------------- prep ----------------
__global__ void split_transpose_kernel(const float* __restrict__ src,
                                       __nv_bfloat16* __restrict__ hi,
                                       __nv_bfloat16* __restrict__ lo) {
    int idx = blockIdx.x * 256 + threadIdx.x;
    int n = idx >> 8, k = idx & 255;
    float x = src[k * 256 + n];
    __nv_bfloat16 h = __float2bfloat16(x);
    hi[idx] = h;
    lo[idx] = __float2bfloat16(x - __bfloat162float(h));
}
__global__ void prep_Uth_kernel(const float* __restrict__ U) {
    int idx = blockIdx.x * 256 + threadIdx.x;
    int n = idx >> 8, k = idx & 255;
    g_Uth[idx] = __float2half(U[k * 256 + n]);
}
__global__ void stories_half_kernel(const float* __restrict__ src) {
    size_t i = ((size_t)blockIdx.x * 256 + threadIdx.x) * 4;
    float4 v = *(const float4*)(src + i);
    __half2* d = (__half2*)(g_storiesh + i);
    d[0] = __float22half2_rn(make_float2(v.x, v.y));
    d[1] = __float22half2_rn(make_float2(v.z, v.w));
}

// ---------------- sentW precompute (bf16 3-pass, fp16 out) ----------------
#define SA_STR 264
#define SA_BYTES (128 * SA_STR * 2)
#define SBC_STR 40
#define SBC_BYTES (256 * SBC_STR * 2)
#define OFF_AHI 0
#define OFF_ALO SA_BYTES
#define OFF_B (2 * SA_BYTES)
#define G_SMEM (OFF_B + 4 * SBC_BYTES + 1024)

__device__ __forceinline__ void g_stage_A(const float* __restrict__ Asrc, char* sm, int tid) {
    __nv_bfloat16* sAhi = (__nv_bfloat16*)(sm + OFF_AHI);
    __nv_bfloat16* sAlo = (__nv_bfloat16*)(sm + OFF_ALO);
    for (int i = tid; i < 128 * 32; i += 512) {
        int row = i >> 5, kq = (i & 31) << 3;
        const float* p = Asrc + row * 256 + kq;
        float4 v0 = *(const float4*)p;
        float4 v1 = *(const float4*)(p + 4);
        uint4 h, l;
        split8(v0, v1, h, l);
        *(uint4*)(sAhi + row * SA_STR + kq) = h;
        *(uint4*)(sAlo + row * SA_STR + kq) = l;
    }
}
__device__ __forceinline__ void g_stage_B(char* sm, const __nv_bfloat16* __restrict__ Bthi,
                                          const __nv_bfloat16* __restrict__ Btlo,
                                          int buf, int kt, int tid) {
    __nv_bfloat16* bh = (__nv_bfloat16*)(sm + OFF_B + buf * 2 * SBC_BYTES);
    __nv_bfloat16* bl = (__nv_bfloat16*)(sm + OFF_B + buf * 2 * SBC_BYTES + SBC_BYTES);
    for (int i = tid; i < 1024; i += 512) {
        int n = i >> 2, g = (i & 3) << 3;
        cpasync16(smem_u32(bh + n * SBC_STR + g), Bthi + n * 256 + kt + g);
        cpasync16(smem_u32(bl + n * SBC_STR + g), Btlo + n * 256 + kt + g);
    }
}

__global__ __launch_bounds__(512, 1) void tc_gemm_kernel(const float* __restrict__ Asrc,
                                                         __half* __restrict__ Cout) {
    extern __shared__ char sm[];
    const int tid = threadIdx.x;
    const int lane = tid & 31, wid = tid >> 5;
    const int wr = wid >> 2, wc = wid & 3;
    const int rb = wr * 32;
    const size_t row0 = (size_t)blockIdx.x * 128;
    const int a_lr = ((lane >> 3) & 1) * 8 + (lane & 7);
    const int a_lc = ((lane >> 4) & 1) * 8;
    const int b_nr = ((lane >> 4) << 3) + (lane & 7);
    const int b_kc = ((lane >> 3) & 1) << 3;
    const unsigned sAhiU = smem_u32(sm + OFF_AHI);
    const unsigned sAloU = smem_u32(sm + OFF_ALO);
    const unsigned sB0 = smem_u32(sm + OFF_B);

    g_stage_A(Asrc + row0 * 256, sm, tid);
    __syncthreads();

    float acc[2][8][4];
#pragma unroll
    for (int i = 0; i < 2; i++)
#pragma unroll
        for (int j = 0; j < 8; j++)
#pragma unroll
            for (int q = 0; q < 4; q++) acc[i][j][q] = 0.f;

    g_stage_B(sm, g_Wthi, g_Wtlo, 0, 0, tid);
    asm volatile("cp.async.commit_group;");

#pragma unroll 2
    for (int c = 0; c < 8; c++) {
        if (c < 7) {
            g_stage_B(sm, g_Wthi, g_Wtlo, (c + 1) & 1, (c + 1) * 32, tid);
            asm volatile("cp.async.commit_group;");
            asm volatile("cp.async.wait_group 1;");
        } else {
            asm volatile("cp.async.wait_group 0;");
        }
        __syncthreads();
        const unsigned sBhiU = sB0 + (c & 1) * 2 * SBC_BYTES;
        const unsigned sBloU = sBhiU + SBC_BYTES;
#pragma unroll
        for (int ks = 0; ks < 2; ks++) {
            int kA = c * 32 + ks * 16;
            unsigned Ah[2][4], Al[2][4];
#pragma unroll
            for (int mi = 0; mi < 2; mi++) {
                unsigned aoff = (unsigned)((rb + mi * 16 + a_lr) * SA_STR + kA + a_lc) * 2;
                ldsm_x4(sAhiU + aoff, Ah[mi][0], Ah[mi][1], Ah[mi][2], Ah[mi][3]);
                ldsm_x4(sAloU + aoff, Al[mi][0], Al[mi][1], Al[mi][2], Al[mi][3]);
            }
#pragma unroll
            for (int np = 0; np < 4; np++) {
                unsigned boff = (unsigned)((wc * 64 + np * 16 + b_nr) * SBC_STR + ks * 16 + b_kc) * 2;
                unsigned Bh[4], Bl[4];
                ldsm_x4(sBhiU + boff, Bh[0], Bh[1], Bh[2], Bh[3]);
                ldsm_x4(sBloU + boff, Bl[0], Bl[1], Bl[2], Bl[3]);
#pragma unroll
                for (int mi = 0; mi < 2; mi++) {
#pragma unroll
                    for (int nj = 0; nj < 2; nj++) {
                        float* cc = acc[mi][np * 2 + nj];
                        mma_bf16(cc, Ah[mi], Bh[2 * nj], Bh[2 * nj + 1]);
                        mma_bf16(cc, Ah[mi], Bl[2 * nj], Bl[2 * nj + 1]);
                        mma_bf16(cc, Al[mi], Bh[2 * nj], Bh[2 * nj + 1]);
                    }
                }
            }
        }
        __syncthreads();
    }

    const int gid = lane >> 2, tig = lane & 3;
#pragma unroll
    for (int mi = 0; mi < 2; mi++) {
        int r0 = rb + mi * 16 + gid, r1 = r0 + 8;
#pragma unroll
        for (int nt = 0; nt < 8; nt++) {
            int C = wc * 64 + nt * 8 + tig * 2;
            float* cc = acc[mi][nt];
            *(__half2*)(Cout + (row0 + r0) * 256 + C) = __float22half2_rn(make_float2(cc[0], cc[1]));
            *(__half2*)(Cout + (row0 + r1) * 256 + C) = __float22half2_rn(make_float2(cc[2], cc[3]));
        }
    }
}

// ================= persistent recurrence (raw fp16 state + carried scale) ==
#define P_SA_STR 264
#define P_SA_BYTES (64 * P_SA_STR * 2)         // 33792
#define P_BH_STR 264
#define P_BH_BYTES (256 * P_BH_STR * 2)        // 135168
#define P_OFF_A 0
#define P_OFF_B P_SA_BYTES
#define P_OFF_F32 (P_OFF_B + P_BH_BYTES)
// f32: keys256 kc256 pa256 gm64 sc64 ss256 g1_256 g2_256
#define P_SMEM (P_OFF_F32 + (256 * 3 + 64 * 2 + 256 * 3) * 4)

__global__ __launch_bounds__(256, 1) void persist_kernel(const float* __restrict__ stories,
                                                         const float* __restrict__ mask,
                                                         const float* __restrict__ keys,
                                                         const float* __restrict__ V,
                                                         const float* __restrict__ prelu_a,
                                                         float* __restrict__ out) {
    extern __shared__ char sm[];
    __half* sA = (__half*)(sm + P_OFF_A);
    __half* sB = (__half*)(sm + P_OFF_B);
    float* sKeys = (float*)(sm + P_OFF_F32);
    float* sKC = sKeys + 256;
    float* sPA = sKC + 256;
    float* sGm = sPA + 256;   // [64]
    float* sSc = sGm + 64;    // [64]
    float* sSS = sSc + 64;    // [64][4]
    float* sG1 = sSS + 256;   // [64][4]
    float* sG2 = sG1 + 256;   // [64][4]

    const int tid = threadIdx.x;
    const int lane = tid & 31, wid = tid >> 5;
    const int wr = wid >> 2, wc = wid & 3;
    const int rb = wr * 32;
    const int gid = lane >> 2, tig = lane & 3;
    const int m = blockIdx.y;
    const int b0 = blockIdx.x * 64;

    const int a_lr = ((lane >> 3) & 1) * 8 + (lane & 7);
    const int a_lc = ((lane >> 4) & 1) * 8;
    const int b_nr = ((lane >> 4) << 3) + (lane & 7);
    const int b_kc = ((lane >> 3) & 1) << 3;
    const unsigned sAU = smem_u32(sA), sBU = smem_u32(sB);

    float* __restrict__ gates_out = out + (size_t)MM * BB * HH;

    sKeys[tid] = keys[m * HH + tid];
    sPA[tid] = prelu_a[tid];
    {   // kc[col] = keys[m,:] . V[:,col]
        float p = 0.f;
        const float* vp = V + tid;
        const float* kp = keys + m * HH;
#pragma unroll 8
        for (int k = 0; k < 256; k++) p += kp[k] * vp[(size_t)k * HH];
        sKC[tid] = p;
    }
    // resident U^T fp16
    for (int i = tid; i < 256 * 32; i += 256) {
        int n = i >> 5, g = (i & 31) << 3;
        *(uint4*)(sB + n * P_BH_STR + g) = *(const uint4*)(g_Uth + n * 256 + g);
    }
    // init state rows = keys[m] raw, scale 1
    for (int i = tid; i < 64 * 32; i += 256) {
        int row = i >> 5, kq = (i & 31) << 3;
#pragma unroll
        for (int j = 0; j < 4; j++) {
            float2 kv = *(const float2*)(keys + m * HH + kq + 2 * j);
            *(uint32_t*)(sA + row * P_SA_STR + kq + 2 * j) = h2u(__float22half2_rn(kv));
        }
    }
    if (tid < 64) sSc[tid] = 1.0f;
    // gate 0: arg = 2 * dot(keys, sent0_row)
    {
        int gr = tid >> 2, gq = tid & 3;
        const float* srow = stories + ((size_t)(b0 + gr)) * HH + gq * 64;
        const float* kk = sKeys + gq * 64;
        float p = 0.f;
#pragma unroll
        for (int k = 0; k < 64; k += 4) {
            float4 sv = *(const float4*)(srow + k);
            p += kk[k] * sv.x + kk[k + 1] * sv.y + kk[k + 2] * sv.z + kk[k + 3] * sv.w;
        }
        p += __shfl_xor_sync(0xffffffffu, p, 1);
        p += __shfl_xor_sync(0xffffffffu, p, 2);
        if (gq == 0) {
            float g = 1.0f / (1.0f + expf(-2.0f * p));
            gates_out[(size_t)m * BB + b0 + gr] = g;
            sGm[gr] = g * mask[b0 + gr];
        }
    }
    __syncthreads();

    for (int t = 0; t < TT; t++) {
        // ---- mma: D = raw_state @ U (barrier-free, single pass) ----
        float acc[2][8][4];
#pragma unroll
        for (int i = 0; i < 2; i++)
#pragma unroll
            for (int j = 0; j < 8; j++)
#pragma unroll
                for (int q = 0; q < 4; q++) acc[i][j][q] = 0.f;

#pragma unroll 4
        for (int ks = 0; ks < 16; ks++) {
            int kcol = ks * 16;
            unsigned Af[2][4];
#pragma unroll
            for (int mi = 0; mi < 2; mi++) {
                unsigned aoff = (unsigned)((rb + mi * 16 + a_lr) * P_SA_STR + kcol + a_lc) * 2;
                ldsm_x4(sAU + aoff, Af[mi][0], Af[mi][1], Af[mi][2], Af[mi][3]);
            }
#pragma unroll
            for (int np = 0; np < 4; np++) {
                unsigned boff = (unsigned)((wc * 64 + np * 16 + b_nr) * P_BH_STR + kcol + b_kc) * 2;
                unsigned Bf[4];
                ldsm_x4(sBU + boff, Bf[0], Bf[1], Bf[2], Bf[3]);
#pragma unroll
                for (int mi = 0; mi < 2; mi++) {
#pragma unroll
                    for (int nj = 0; nj < 2; nj++)
                        mma_f16(acc[mi][np * 2 + nj], Af[mi], Bf[2 * nj], Bf[2 * nj + 1]);
                }
            }
        }
        __syncthreads();   // all warps done reading sA

        // ---- fused epilogue + next-gate partials ----
        const int tn = (t < TT - 1) ? t + 1 : t;
        const __half* swb = g_sentWh + ((size_t)t * BB + b0) * HH;
        const __half* seb = g_storiesh + ((size_t)tn * BB + b0) * HH;
#pragma unroll
        for (int mi = 0; mi < 2; mi++) {
            int r0 = rb + mi * 16 + gid, r1 = r0 + 8;
            float gm0 = sGm[r0], gm1 = sGm[r1];
            float s0 = sSc[r0], s1 = sSc[r1];
            float ss0 = 0.f, ss1 = 0.f, g1a = 0.f, g1b = 0.f, g2a = 0.f, g2b = 0.f;
#pragma unroll
            for (int nt = 0; nt < 8; nt++) {
                int C = wc * 64 + nt * 8 + tig * 2;
                float2 kc = *(const float2*)(sKC + C);
                float2 pa = *(const float2*)(sPA + C);
                float2 kv = *(const float2*)(sKeys + C);
                float2 sw0 = __half22float2(*(const __half2*)(swb + (size_t)r0 * 256 + C));
                float2 sw1 = __half22float2(*(const __half2*)(swb + (size_t)r1 * 256 + C));
                float2 se0 = __half22float2(*(const __half2*)(seb + (size_t)r0 * 256 + C));
                float2 se1 = __half22float2(*(const __half2*)(seb + (size_t)r1 * 256 + C));
                float2 o0 = __half22float2(u2h(*(const uint32_t*)(sA + r0 * P_SA_STR + C)));
                float2 o1 = __half22float2(u2h(*(const uint32_t*)(sA + r1 * P_SA_STR + C)));
                float* cc = acc[mi][nt];
                float v, n0x, n0y, n1x, n1y;
                v = fmaf(s0, cc[0], kc.x + sw0.x); v = (v >= 0.f) ? v : pa.x * v; n0x = fmaf(gm0, v, s0 * o0.x);
                v = fmaf(s0, cc[1], kc.y + sw0.y); v = (v >= 0.f) ? v : pa.y * v; n0y = fmaf(gm0, v, s0 * o0.y);
                v = fmaf(s1, cc[2], kc.x + sw1.x); v = (v >= 0.f) ? v : pa.x * v; n1x = fmaf(gm1, v, s1 * o1.x);
                v = fmaf(s1, cc[3], kc.y + sw1.y); v = (v >= 0.f) ? v : pa.y * v; n1y = fmaf(gm1, v, s1 * o1.y);
                ss0 = fmaf(n0x, n0x, fmaf(n0y, n0y, ss0));
                ss1 = fmaf(n1x, n1x, fmaf(n1y, n1y, ss1));
                g1a = fmaf(n0x, se0.x, fmaf(n0y, se0.y, g1a));
                g1b = fmaf(n1x, se1.x, fmaf(n1y, se1.y, g1b));
                g2a = fmaf(kv.x, se0.x, fmaf(kv.y, se0.y, g2a));
                g2b = fmaf(kv.x, se1.x, fmaf(kv.y, se1.y, g2b));
                *(uint32_t*)(sA + r0 * P_SA_STR + C) = h2u(__float22half2_rn(make_float2(n0x, n0y)));
                *(uint32_t*)(sA + r1 * P_SA_STR + C) = h2u(__float22half2_rn(make_float2(n1x, n1y)));
            }
#pragma unroll
            for (int d = 1; d <= 2; d <<= 1) {
                ss0 += __shfl_xor_sync(0xffffffffu, ss0, d);
                ss1 += __shfl_xor_sync(0xffffffffu, ss1, d);
                g1a += __shfl_xor_sync(0xffffffffu, g1a, d);
                g1b += __shfl_xor_sync(0xffffffffu, g1b, d);
                g2a += __shfl_xor_sync(0xffffffffu, g2a, d);
                g2b += __shfl_xor_sync(0xffffffffu, g2b, d);
            }
            if (tig == 0) {
                sSS[r0 * 4 + wc] = ss0; sSS[r1 * 4 + wc] = ss1;
                sG1[r0 * 4 + wc] = g1a; sG1[r1 * 4 + wc] = g1b;
                sG2[r0 * 4 + wc] = g2a; sG2[r1 * 4 + wc] = g2b;
            }
        }
        __syncthreads();   // sSS/sG1/sG2 + new sA ready

        // ---- finalize: norm scale + next gate ----
        if (tid < 64) {
            int r = tid;
            float ssum = sSS[r * 4] + sSS[r * 4 + 1] + sSS[r * 4 + 2] + sSS[r * 4 + 3];
            float sc = 1.0f / fmaxf(sqrtf(ssum), 1e-12f);
            sSc[r] = sc;
            if (t < TT - 1) {
                float arg = sc * (sG1[r * 4] + sG1[r * 4 + 1] + sG1[r * 4 + 2] + sG1[r * 4 + 3])
                          + (sG2[r * 4] + sG2[r * 4 + 1] + sG2[r * 4 + 2] + sG2[r * 4 + 3]);
                float g = 1.0f / (1.0f + expf(-arg));
                gates_out[((size_t)(t + 1) * MM + m) * BB + b0 + r] = g;
                sGm[r] = g * mask[(t + 1) * BB + b0 + r];
            }
        }
        // no barrier needed here: next mma reads sA (post-barrier above);
        // sSc/sGm consumed only after next iteration's barrier.
    }
    __syncthreads();

    // final output: normalized state
    for (int i = tid; i < 64 * 256; i += 256) {
        int row = i >> 8, col = i & 255;
        float v = __half2float(sA[row * P_SA_STR + col]) * sSc[row];
        out[((size_t)m * BB + b0 + row) * HH + col] = v;
    }
}

// ---------------------------------------------------------------------------
extern "C" void kernel_launch(void* const* d_in, const int* in_sizes, int n_in,
                              void* d_out, int out_size) {
    const float* stories = (const float*)d_in[0];
    const float* mask    = (const float*)d_in[1];
    const float* keys    = (const float*)d_in[2];
    const float* U       = (const float*)d_in[3];
    const float* W       = (const float*)d_in[4];
    const float* V       = (const float*)d_in[5];
    const float* prelu_a = (const float*)d_in[6];
    float* out = (float*)d_out;

    static bool attr_done = false;
    if (!attr_done) {
        cudaFuncSetAttribute(tc_gemm_kernel, cudaFuncAttributeMaxDynamicSharedMemorySize, G_SMEM);
        cudaFuncSetAttribute(persist_kernel, cudaFuncAttributeMaxDynamicSharedMemorySize, P_SMEM);
        attr_done = true;
    }

    __nv_bfloat16 *wthi, *wtlo;
    cudaGetSymbolAddress((void**)&wthi, g_Wthi);
    cudaGetSymbolAddress((void**)&wtlo, g_Wtlo);
    __half* sentwh;
    cudaGetSymbolAddress((void**)&sentwh, g_sentWh);

    split_transpose_kernel<<<256, 256>>>(W, wthi, wtlo);
    prep_Uth_kernel<<<256, 256>>>(U);
    stories_half_kernel<<<(TT * BB * HH) / 1024, 256>>>(stories);
    tc_gemm_kernel<<<(TT * BB) / 128, 512, G_SMEM>>>(stories, sentwh);

    dim3 grid(BB / 64, MM);
    persist_kernel<<<grid, 256, P_SMEM>>>(stories, mask, keys, V, prelu_a, out);
}